// round 13
// baseline (speedup 1.0000x reference)
#include <cuda_runtime.h>
#include <cuda_fp16.h>
#include <math.h>

#define NN 20000
#define NE 320000
#define NR 200
#define DL 16
#define G  64
#define DW 300
#define DH 256
#define HD 128
#define NC 2000
#define VD 30000
#define BB 4
#define TT 32
#define G3 (3*HD)    // 384
#define BG (BB*G)    // 256
#define H1 1024
#define FEAT (G+DH)  // 320
#define RB 296       // rgcn blocks

// k_gru dyn smem: gx + hs4 + gh + msk
#define SMEM_GRU (BB*TT*G3*4 + HD*16 + BB*G3*4 + BB*TT*4)   // 205312

// ---------------- scratch ----------------
__device__ float g_gx[2][BB][TT][G3];
__device__ float g_qemb[BB][DH];
__device__ float g_qg[BB][G];
__device__ float4 g_S[VD];           // per-vocab attention scores (b0..b3)
__device__ __half2 g_nf0h[NN][BG/2];
__device__ float g_sacc[NN][BG];
__device__ int   g_deg[NN];          // statically zero; re-zeroed by k_scan
__device__ int   g_off[NN+1];
__device__ int   g_cur[NN];
__device__ int   g_psrc[NE];
__device__ float g_pw[NE];
__device__ float g_pm[RB][BB];       // per-block softmax max
__device__ float g_pden[RB][BB];     // per-block softmax denom
__device__ float g_pagg[RB][BB][G];  // per-block weighted agg
__device__ float g_hidp[4][BB][H1];

// ---------------- helpers ----------------
__device__ __forceinline__ float sigm(float x) { return 1.f / (1.f + __expf(-x)); }
__device__ __forceinline__ float tanh_fast(float x) { return 2.f / (1.f + __expf(-2.f * x)) - 1.f; }

__device__ __forceinline__ void fma2(unsigned long long& d, unsigned long long a,
                                     unsigned long long b, unsigned long long c) {
    asm("fma.rn.f32x2 %0, %1, %2, %3;" : "=l"(d) : "l"(a), "l"(b), "l"(c));
}
__device__ __forceinline__ void add2(unsigned long long& d, unsigned long long a,
                                     unsigned long long b) {
    asm("add.rn.f32x2 %0, %1, %2;" : "=l"(d) : "l"(a), "l"(b));
}
__device__ __forceinline__ unsigned long long pk2(float x, float y) {
    unsigned long long r; asm("mov.b64 %0, {%1, %2};" : "=l"(r) : "f"(x), "f"(y)); return r;
}
__device__ __forceinline__ float2 upk2(unsigned long long v) {
    float2 f; asm("mov.b64 {%0, %1}, %2;" : "=f"(f.x), "=f"(f.y) : "l"(v)); return f;
}

// ---------------- kernels ----------------

// input gates gx = x @ Wx + bx.  64 blocks x 384 threads.
// EXPLICIT double-buffered Wx loads: next batch loaded before current consumed.
__global__ __launch_bounds__(G3) void k_gx(const int* __restrict__ q,
                     const float* __restrict__ embw,
                     const float* __restrict__ WxF, const float* __restrict__ bxF,
                     const float* __restrict__ WxB, const float* __restrict__ bxB) {
    int d = blockIdx.x >> 5;
    int grp = blockIdx.x & 31;
    const float* Wx = d ? WxB : WxF;
    const float* bx = d ? bxB : bxF;
    __shared__ unsigned long long xs01[DW];
    __shared__ unsigned long long xs23[DW];
    int bt0 = grp * 4;
    int tok0 = q[((bt0 + 0) >> 5) * TT + ((bt0 + 0) & 31)];
    int tok1 = q[((bt0 + 1) >> 5) * TT + ((bt0 + 1) & 31)];
    int tok2 = q[((bt0 + 2) >> 5) * TT + ((bt0 + 2) & 31)];
    int tok3 = q[((bt0 + 3) >> 5) * TT + ((bt0 + 3) & 31)];
    for (int k = threadIdx.x; k < DW; k += blockDim.x) {
        float e0 = embw[tok0 * DW + k];
        float e1 = embw[tok1 * DW + k];
        float e2 = embw[tok2 * DW + k];
        float e3 = embw[tok3 * DW + k];
        xs01[k] = pk2(e0, e1);
        xs23[k] = pk2(e2, e3);
    }
    __syncthreads();
    int j = threadIdx.x;
    float bj = bx[j];
    unsigned long long a01 = pk2(bj, bj), a23 = a01;
    float wv[10];
    #pragma unroll
    for (int i = 0; i < 10; i++) wv[i] = Wx[i * G3 + j];
    #pragma unroll 1
    for (int k0 = 0; k0 < DW; k0 += 10) {
        float wn[10];
        int kn = (k0 + 10 < DW) ? (k0 + 10) : k0;   // clamped (harmless reload on last)
        #pragma unroll
        for (int i = 0; i < 10; i++) wn[i] = Wx[(kn + i) * G3 + j];
        #pragma unroll
        for (int i = 0; i < 10; i++) {
            unsigned long long wd = pk2(wv[i], wv[i]);
            fma2(a01, xs01[k0 + i], wd, a01);
            fma2(a23, xs23[k0 + i], wd, a23);
        }
        #pragma unroll
        for (int i = 0; i < 10; i++) wv[i] = wn[i];
    }
    float2 f01 = upk2(a01), f23 = upk2(a23);
    g_gx[d][(bt0 + 0) >> 5][(bt0 + 0) & 31][j] = f01.x;
    g_gx[d][(bt0 + 1) >> 5][(bt0 + 1) & 31][j] = f01.y;
    g_gx[d][(bt0 + 2) >> 5][(bt0 + 2) & 31][j] = f23.x;
    g_gx[d][(bt0 + 3) >> 5][(bt0 + 3) & 31][j] = f23.y;
}

// GRU recurrence. 2 blocks x 384 threads; Wh register-resident; gx+masks in smem.
// Accumulators split into 2 interleaved chains per batch-pair to halve RAW depth.
__global__ __launch_bounds__(G3, 1) void k_gru(const int* __restrict__ q,
                      const float* __restrict__ WhF, const float* __restrict__ bhF,
                      const float* __restrict__ WhB, const float* __restrict__ bhB) {
    extern __shared__ float sm[];
    float* gx_s = sm;                                       // [BB*TT*G3]
    ulonglong2* hs4 = (ulonglong2*)(sm + BB * TT * G3);     // [HD]
    float* gh = (float*)(hs4 + HD);                         // [BB*G3]
    int* msk = (int*)(gh + BB * G3);                        // [BB*TT]
    int d = blockIdx.x;
    const float* Wh = d ? WhB : WhF;
    const float* bh = d ? bhB : bhF;
    int tid = threadIdx.x;
    {
        const float4* src = (const float4*)&g_gx[d][0][0][0];
        float4* dst = (float4*)gx_s;
        #pragma unroll
        for (int i = 0; i < 32; i++) dst[i * G3 + tid] = src[i * G3 + tid];
    }
    if (tid < BB * TT) msk[tid] = (q[tid] != 0);
    if (tid < HD) hs4[tid] = make_ulonglong2(0ull, 0ull);
    float w[HD];
    #pragma unroll
    for (int k = 0; k < HD; k++) w[k] = Wh[k * G3 + tid];
    float bj = bh[tid];
    unsigned long long bj2 = pk2(bj, bj);
    const unsigned long long z2 = pk2(0.f, 0.f);
    __syncthreads();
    for (int s = 0; s < TT; s++) {
        int t = d ? (TT - 1 - s) : s;
        unsigned long long a01a = bj2, a01b = z2, a23a = bj2, a23b = z2;
        #pragma unroll
        for (int k = 0; k < HD; k += 2) {
            unsigned long long wd0 = pk2(w[k], w[k]);
            ulonglong2 hv0 = hs4[k];
            fma2(a01a, hv0.x, wd0, a01a);
            fma2(a23a, hv0.y, wd0, a23a);
            unsigned long long wd1 = pk2(w[k + 1], w[k + 1]);
            ulonglong2 hv1 = hs4[k + 1];
            fma2(a01b, hv1.x, wd1, a01b);
            fma2(a23b, hv1.y, wd1, a23b);
        }
        unsigned long long a01, a23;
        add2(a01, a01a, a01b);
        add2(a23, a23a, a23b);
        float2 f01 = upk2(a01), f23 = upk2(a23);
        gh[0 * G3 + tid] = f01.x; gh[1 * G3 + tid] = f01.y;
        gh[2 * G3 + tid] = f23.x; gh[3 * G3 + tid] = f23.y;
        __syncthreads();
        for (int u = tid; u < BB * HD; u += G3) {
            int b = u >> 7, i = u & 127;
            const float* gx = &gx_s[(b * TT + t) * G3];
            float r = sigm(gx[i] + gh[b * G3 + i]);
            float z = sigm(gx[HD + i] + gh[b * G3 + HD + i]);
            float n = tanh_fast(gx[2 * HD + i] + r * gh[b * G3 + 2 * HD + i]);
            float hold = ((float*)hs4)[i * 4 + b];
            float hn = (1.f - z) * n + z * hold;
            if (msk[b * TT + t]) ((float*)hs4)[i * 4 + b] = hn;
        }
        __syncthreads();
    }
    for (int u = tid; u < BB * HD; u += G3) {
        int b = u >> 7, i = u & 127;
        g_qemb[b][d * HD + i] = ((float*)hs4)[i * 4 + b];
    }
}

// qg (block-redundant) + per-vocab scores S[v][b] = qg[b] . emb_desc[v].
__global__ void k_svqg(const float* __restrict__ embd,
                       const float* __restrict__ Whg, const float* __restrict__ bhg) {
    __shared__ float qs[BB][G];
    int tid = threadIdx.x;
    {
        int b = tid >> 6, g = tid & 63;
        float acc = bhg[g];
        #pragma unroll 8
        for (int k = 0; k < DH; k++) acc = fmaf(g_qemb[b][k], Whg[k * G + g], acc);
        qs[b][g] = acc;
        if (blockIdx.x == 0) g_qg[b][g] = acc;
    }
    __syncthreads();
    int v = blockIdx.x * 256 + tid;
    if (v >= VD) return;
    float s0 = 0.f, s1 = 0.f, s2 = 0.f, s3 = 0.f;
    const float4* row = (const float4*)&embd[v * G];
    #pragma unroll
    for (int g4 = 0; g4 < G / 4; g4++) {
        float4 e = row[g4];
        float4 q0 = *(float4*)&qs[0][g4 * 4];
        float4 q1 = *(float4*)&qs[1][g4 * 4];
        float4 q2 = *(float4*)&qs[2][g4 * 4];
        float4 q3 = *(float4*)&qs[3][g4 * 4];
        s0 += e.x * q0.x + e.y * q0.y + e.z * q0.z + e.w * q0.w;
        s1 += e.x * q1.x + e.y * q1.y + e.z * q1.z + e.w * q1.w;
        s2 += e.x * q2.x + e.y * q2.y + e.z * q2.z + e.w * q2.w;
        s3 += e.x * q3.x + e.y * q3.y + e.z * q3.z + e.w * q3.w;
    }
    g_S[v] = make_float4(s0, s1, s2, s3);
}

// desc attention -> nf0 (half2 out). Warp/node; scores via S-table lookup.
#define NFW 8
__global__ void k_nf0(const int* __restrict__ descs, const float* __restrict__ embd) {
    __shared__ float attnw[NFW][DL][BB];
    int tid = threadIdx.x, lane = tid & 31, wl = tid >> 5;
    int n = blockIdx.x * NFW + wl;
    int t16 = lane & 15, half = lane >> 4;
    int tok = descs[n * DL + t16];
    float4 sv = g_S[tok];
    float sa = half ? sv.y : sv.x;   // batch = half
    float sb = half ? sv.w : sv.z;   // batch = half + 2
    float ma = sa, mb = sb;
    #pragma unroll
    for (int o = 1; o < 16; o <<= 1) {
        ma = fmaxf(ma, __shfl_xor_sync(0xFFFFFFFFu, ma, o));
        mb = fmaxf(mb, __shfl_xor_sync(0xFFFFFFFFu, mb, o));
    }
    float ea = __expf(sa - ma), eb = __expf(sb - mb);
    float da = ea, db = eb;
    #pragma unroll
    for (int o = 1; o < 16; o <<= 1) {
        da += __shfl_xor_sync(0xFFFFFFFFu, da, o);
        db += __shfl_xor_sync(0xFFFFFFFFu, db, o);
    }
    attnw[wl][t16][half]     = ea / da;
    attnw[wl][t16][2 + half] = eb / db;
    __syncwarp();
    float o00 = 0.f, o01 = 0.f, o10 = 0.f, o11 = 0.f;
    float o20 = 0.f, o21 = 0.f, o30 = 0.f, o31 = 0.f;
    #pragma unroll
    for (int t = 0; t < DL; t++) {
        int tk = __shfl_sync(0xFFFFFFFFu, tok, t);
        float2 x = *(const float2*)&embd[tk * G + 2 * lane];
        float4 w4 = *(float4*)&attnw[wl][t][0];
        o00 = fmaf(w4.x, x.x, o00); o01 = fmaf(w4.x, x.y, o01);
        o10 = fmaf(w4.y, x.x, o10); o11 = fmaf(w4.y, x.y, o11);
        o20 = fmaf(w4.z, x.x, o20); o21 = fmaf(w4.z, x.y, o21);
        o30 = fmaf(w4.w, x.x, o30); o31 = fmaf(w4.w, x.y, o31);
    }
    g_nf0h[n][0 * 32 + lane] = __floats2half2_rn(o00, o01);
    g_nf0h[n][1 * 32 + lane] = __floats2half2_rn(o10, o11);
    g_nf0h[n][2 * 32 + lane] = __floats2half2_rn(o20, o21);
    g_nf0h[n][3 * 32 + lane] = __floats2half2_rn(o30, o31);
}

__global__ void k_deg(const int* __restrict__ dst) {
    int e = blockIdx.x * blockDim.x + threadIdx.x;
    if (e < NE) atomicAdd(&g_deg[dst[e]], 1);
}

// single-block warp-shfl exclusive scan; re-zeroes g_deg for next replay
__global__ void k_scan() {
    __shared__ int wsum[32];
    __shared__ int carry;
    int tid = threadIdx.x, lane = tid & 31, wid = tid >> 5;
    if (tid == 0) carry = 0;
    __syncthreads();
    for (int base = 0; base < NN; base += 1024) {
        int idx = base + tid;
        int v = (idx < NN) ? g_deg[idx] : 0;
        if (idx < NN) g_deg[idx] = 0;
        int x = v;
        #pragma unroll
        for (int o = 1; o < 32; o <<= 1) {
            int y = __shfl_up_sync(0xFFFFFFFFu, x, o);
            if (lane >= o) x += y;
        }
        if (lane == 31) wsum[wid] = x;
        __syncthreads();
        if (wid == 0) {
            int s = wsum[lane];
            #pragma unroll
            for (int o = 1; o < 32; o <<= 1) {
                int y = __shfl_up_sync(0xFFFFFFFFu, s, o);
                if (lane >= o) s += y;
            }
            wsum[lane] = s;
        }
        __syncthreads();
        int ex = carry + (wid ? wsum[wid - 1] : 0) + x - v;
        if (idx < NN) { g_off[idx] = ex; g_cur[idx] = ex; }
        __syncthreads();
        if (tid == 0) carry += wsum[31];
        __syncthreads();
    }
    if (tid == 0) g_off[NN] = carry;
}

__global__ void k_perm(const int* __restrict__ src, const int* __restrict__ dst,
                       const int* __restrict__ et, const float* __restrict__ wcomp) {
    int e = blockIdx.x * blockDim.x + threadIdx.x;
    if (e >= NE) return;
    int pos = atomicAdd(&g_cur[dst[e]], 1);
    g_psrc[pos] = src[e];
    g_pw[pos]   = wcomp[et[e]];
}

// edge aggregation: 2 warps per dst node (warp owns a batch pair); lane owns 8B.
__global__ void k_agg() {
    int gw = (blockIdx.x * blockDim.x + threadIdx.x) >> 5;
    int lane = threadIdx.x & 31;
    if (gw >= NN * 2) return;
    int n = gw >> 1, hb = gw & 1;
    int beg = g_off[n], end = g_off[n + 1];
    float a0 = 0.f, a1 = 0.f, a2 = 0.f, a3 = 0.f;
    int poff = hb * 64 + lane * 2;
    for (int i = beg; i < end; i++) {
        int s = g_psrc[i];
        float w = g_pw[i];
        uint2 v = *(const uint2*)&g_nf0h[s][poff];
        __half2 h0 = *(__half2*)&v.x, h1 = *(__half2*)&v.y;
        float2 f0 = __half22float2(h0), f1 = __half22float2(h1);
        a0 = fmaf(w, f0.x, a0); a1 = fmaf(w, f0.y, a1);
        a2 = fmaf(w, f1.x, a2); a3 = fmaf(w, f1.y, a3);
    }
    *(float4*)&g_sacc[n][hb * 128 + lane * 4] = make_float4(a0, a1, a2, a3);
}

// nf1 = relu(s @ bases + bias) fused with ONLINE-SOFTMAX attention pooling.
__global__ void k_rgcn(const float* __restrict__ bases, const float* __restrict__ bias) {
    __shared__ float bs[G * G];
    __shared__ float srow[BG];
    __shared__ float swred[8];
    __shared__ float sv_s[BB];
    int tid = threadIdx.x;   // 256
    for (int i = tid; i < G * G; i += 256) bs[i] = bases[i];
    int b = tid >> 6, g = tid & 63;
    float bia = bias[g];
    float qv = g_qg[b][g];
    float m_run = -3.0e38f, den = 0.f, aggr = 0.f;
    __syncthreads();
    for (int n = blockIdx.x; n < NN; n += RB) {
        srow[tid] = g_sacc[n][tid];
        __syncthreads();
        float acc = bia;
        const float* sb = &srow[b * G];
        #pragma unroll 8
        for (int k = 0; k < G; k++) acc = fmaf(sb[k], bs[k * G + g], acc);
        acc = fmaxf(acc, 0.f);
        float p = acc * qv;
        p += __shfl_xor_sync(0xFFFFFFFFu, p, 16);
        p += __shfl_xor_sync(0xFFFFFFFFu, p, 8);
        p += __shfl_xor_sync(0xFFFFFFFFu, p, 4);
        p += __shfl_xor_sync(0xFFFFFFFFu, p, 2);
        p += __shfl_xor_sync(0xFFFFFFFFu, p, 1);
        if ((tid & 31) == 0) swred[tid >> 5] = p;
        __syncthreads();
        if (tid < BB) sv_s[tid] = swred[2 * tid] + swred[2 * tid + 1];
        __syncthreads();
        float sv = sv_s[b];
        float m_new = fmaxf(m_run, sv);
        float sc = __expf(m_run - m_new);
        float e = __expf(sv - m_new);
        aggr = aggr * sc + e * acc;
        den  = den * sc + e;
        m_run = m_new;
    }
    g_pagg[blockIdx.x][b][g] = aggr;
    if (g == 0) { g_pden[blockIdx.x][b] = den; g_pm[blockIdx.x][b] = m_run; }
}

// hidden partials: 32 blocks = (hblk 0..7) x (kp 0..3); 128 threads.
// kp==0 blocks fuse the softmax-partial combine (pool) inline.
__global__ void k_hidden(const float* __restrict__ W1) {
    int hb = blockIdx.x >> 2, kp = blockIdx.x & 3;
    int tid = threadIdx.x;
    int h = hb * 128 + tid;
    int k0 = kp * 80;
    __shared__ float feat[BB][80];
    if (kp == 0) {
        for (int i = tid; i < BB * 80; i += 128) {
            int b = i / 80, kk = i % 80;
            if (kk < G) {
                float m = -3.0e38f;
                #pragma unroll 4
                for (int r = 0; r < RB; r++) m = fmaxf(m, g_pm[r][b]);
                float acc = 0.f, den = 0.f;
                #pragma unroll 4
                for (int r = 0; r < RB; r++) {
                    float sc = __expf(g_pm[r][b] - m);
                    acc = fmaf(g_pagg[r][b][kk], sc, acc);
                    den = fmaf(g_pden[r][b], sc, den);
                }
                feat[b][kk] = acc / den;
            } else {
                feat[b][kk] = g_qemb[b][kk - G];
            }
        }
    } else {
        for (int i = tid; i < BB * 80; i += 128) {
            int b = i / 80, kk = i % 80;
            feat[b][kk] = g_qemb[b][k0 + kk - G];
        }
    }
    __syncthreads();
    float a0 = 0.f, a1 = 0.f, a2 = 0.f, a3 = 0.f;
    #pragma unroll 4
    for (int kk = 0; kk < 80; kk++) {
        float w = W1[(k0 + kk) * H1 + h];
        a0 = fmaf(feat[0][kk], w, a0);
        a1 = fmaf(feat[1][kk], w, a1);
        a2 = fmaf(feat[2][kk], w, a2);
        a3 = fmaf(feat[3][kk], w, a3);
    }
    g_hidp[kp][0][h] = a0; g_hidp[kp][1][h] = a1;
    g_hidp[kp][2][h] = a2; g_hidp[kp][3][h] = a3;
}

// logits: 63 blocks x 512 (16 k-parts x 32 classes); relu+bias fused.
__global__ void k_logits(const float* __restrict__ W2, const float* __restrict__ b1,
                         const float* __restrict__ b2, float* __restrict__ out) {
    __shared__ float hsm[BB][H1];
    __shared__ float red[16][32][BB];
    int tid = threadIdx.x;
    for (int i = tid; i < BB * H1; i += 512) {
        int b = i >> 10, k = i & (H1 - 1);
        float v = g_hidp[0][b][k] + g_hidp[1][b][k] + g_hidp[2][b][k] + g_hidp[3][b][k] + b1[k];
        hsm[b][k] = fmaxf(v, 0.f);
    }
    __syncthreads();
    int kp = tid >> 5, cl = tid & 31;
    int c = blockIdx.x * 32 + cl;
    float a0 = 0.f, a1 = 0.f, a2 = 0.f, a3 = 0.f;
    if (c < NC) {
        int k0 = kp * 64;
        #pragma unroll 4
        for (int k = k0; k < k0 + 64; k++) {
            float w = W2[k * NC + c];
            a0 = fmaf(hsm[0][k], w, a0);
            a1 = fmaf(hsm[1][k], w, a1);
            a2 = fmaf(hsm[2][k], w, a2);
            a3 = fmaf(hsm[3][k], w, a3);
        }
    }
    red[kp][cl][0] = a0; red[kp][cl][1] = a1; red[kp][cl][2] = a2; red[kp][cl][3] = a3;
    __syncthreads();
    if (kp == 0 && c < NC) {
        float bb2 = b2[c];
        #pragma unroll
        for (int b = 0; b < BB; b++) {
            float s = bb2;
            #pragma unroll
            for (int p = 0; p < 16; p++) s += red[p][cl][b];
            out[b * NC + c] = s;
        }
    }
}

// ---------------- launch ----------------
extern "C" void kernel_launch(void* const* d_in, const int* in_sizes, int n_in,
                              void* d_out, int out_size) {
    const int*   questions = (const int*)d_in[0];
    const int*   node_descs= (const int*)d_in[1];
    const int*   edge_src  = (const int*)d_in[2];
    const int*   edge_dst  = (const int*)d_in[3];
    const int*   edge_type = (const int*)d_in[4];
    const float* emb_word  = (const float*)d_in[5];
    const float* emb_desc  = (const float*)d_in[6];
    const float* Wx_f = (const float*)d_in[7];
    const float* Wh_f = (const float*)d_in[8];
    const float* bx_f = (const float*)d_in[9];
    const float* bh_f = (const float*)d_in[10];
    const float* Wx_b = (const float*)d_in[11];
    const float* Wh_b = (const float*)d_in[12];
    const float* bx_b = (const float*)d_in[13];
    const float* bh_b = (const float*)d_in[14];
    const float* W_hg = (const float*)d_in[15];
    const float* b_hg = (const float*)d_in[16];
    const float* bases = (const float*)d_in[17];
    const float* w_comp = (const float*)d_in[18];
    const float* rgcn_bias = (const float*)d_in[19];
    const float* W1 = (const float*)d_in[20];
    const float* b1 = (const float*)d_in[21];
    const float* W2 = (const float*)d_in[22];
    const float* b2 = (const float*)d_in[23];
    float* out = (float*)d_out;

    static cudaStream_t s1 = nullptr;
    static cudaEvent_t ev0 = nullptr, ev1 = nullptr;
    if (!s1) {
        cudaStreamCreateWithFlags(&s1, cudaStreamNonBlocking);
        cudaEventCreateWithFlags(&ev0, cudaEventDisableTiming);
        cudaEventCreateWithFlags(&ev1, cudaEventDisableTiming);
        cudaFuncSetAttribute(k_gru, cudaFuncAttributeMaxDynamicSharedMemorySize, SMEM_GRU);
    }

    // fork s1 (CSR chain: input-only deps) to run fully under gx/gru
    cudaEventRecord(ev0, 0);
    cudaStreamWaitEvent(s1, ev0, 0);

    k_deg<<<(NE + 255) / 256, 256, 0, s1>>>(edge_dst);                     // 1
    k_scan<<<1, 1024, 0, s1>>>();                                          // 2
    k_gx<<<64, G3>>>(questions, emb_word, Wx_f, bx_f, Wx_b, bx_b);        // 3
    k_gru<<<2, G3, SMEM_GRU>>>(questions, Wh_f, bh_f, Wh_b, bh_b);        // 4 (ncu slot)
    k_perm<<<(NE + 255) / 256, 256, 0, s1>>>(edge_src, edge_dst, edge_type, w_comp); // 5
    cudaEventRecord(ev1, s1);
    k_svqg<<<(VD + 255) / 256, 256>>>(emb_desc, W_hg, b_hg);               // 6
    k_nf0<<<NN / NFW, 256>>>(node_descs, emb_desc);                        // 7
    cudaStreamWaitEvent(0, ev1, 0);
    k_agg<<<(NN * 2 * 32 + 255) / 256, 256>>>();                           // 8
    k_rgcn<<<RB, 256>>>(bases, rgcn_bias);                                 // 9
    k_hidden<<<32, 128>>>(W1);                                             // 10
    k_logits<<<63, 512>>>(W2, b1, b2, out);                                // 11
}

// round 14
// speedup vs baseline: 1.0153x; 1.0153x over previous
#include <cuda_runtime.h>
#include <cuda_fp16.h>
#include <math.h>

#define NN 20000
#define NE 320000
#define NR 200
#define DL 16
#define G  64
#define DW 300
#define DH 256
#define HD 128
#define NC 2000
#define VD 30000
#define BB 4
#define TT 32
#define G3 (3*HD)    // 384
#define BG (BB*G)    // 256
#define H1 1024
#define FEAT (G+DH)  // 320
#define RB 296       // rgcn blocks

// k_gru dyn smem: gx + hs4 + gh + msk
#define SMEM_GRU (BB*TT*G3*4 + HD*16 + BB*G3*4 + BB*TT*4)   // 205312

// ---------------- scratch ----------------
__device__ float g_gx[2][BB][TT][G3];
__device__ float g_qemb[BB][DH];
__device__ float g_qg[BB][G];
__device__ float4 g_S[VD];           // per-vocab attention scores (b0..b3)
__device__ __half2 g_nf0h[NN][BG/2];
__device__ float g_sacc[NN][BG];
__device__ int   g_deg[NN];          // statically zero; re-zeroed by k_scan
__device__ int   g_off[NN+1];
__device__ int   g_cur[NN];
__device__ int   g_psrc[NE];
__device__ float g_pw[NE];
__device__ float g_pm[RB][BB];       // per-block softmax max
__device__ float g_pden[RB][BB];     // per-block softmax denom
__device__ float g_pagg[RB][BB][G];  // per-block weighted agg
__device__ float g_hidp[4][BB][H1];

// ---------------- helpers ----------------
__device__ __forceinline__ float sigm(float x) { return 1.f / (1.f + __expf(-x)); }
__device__ __forceinline__ float tanh_fast(float x) { return 2.f / (1.f + __expf(-2.f * x)) - 1.f; }

__device__ __forceinline__ void fma2(unsigned long long& d, unsigned long long a,
                                     unsigned long long b, unsigned long long c) {
    asm("fma.rn.f32x2 %0, %1, %2, %3;" : "=l"(d) : "l"(a), "l"(b), "l"(c));
}
__device__ __forceinline__ unsigned long long pk2(float x, float y) {
    unsigned long long r; asm("mov.b64 %0, {%1, %2};" : "=l"(r) : "f"(x), "f"(y)); return r;
}
__device__ __forceinline__ float2 upk2(unsigned long long v) {
    float2 f; asm("mov.b64 {%0, %1}, %2;" : "=f"(f.x), "=f"(f.y) : "l"(v)); return f;
}

// ---------------- kernels ----------------

// input gates gx = x @ Wx + bx.  64 blocks x 384 threads; double-buffered Wx loads.
__global__ __launch_bounds__(G3) void k_gx(const int* __restrict__ q,
                     const float* __restrict__ embw,
                     const float* __restrict__ WxF, const float* __restrict__ bxF,
                     const float* __restrict__ WxB, const float* __restrict__ bxB) {
    int d = blockIdx.x >> 5;
    int grp = blockIdx.x & 31;
    const float* Wx = d ? WxB : WxF;
    const float* bx = d ? bxB : bxF;
    __shared__ unsigned long long xs01[DW];
    __shared__ unsigned long long xs23[DW];
    int bt0 = grp * 4;
    int tok0 = q[((bt0 + 0) >> 5) * TT + ((bt0 + 0) & 31)];
    int tok1 = q[((bt0 + 1) >> 5) * TT + ((bt0 + 1) & 31)];
    int tok2 = q[((bt0 + 2) >> 5) * TT + ((bt0 + 2) & 31)];
    int tok3 = q[((bt0 + 3) >> 5) * TT + ((bt0 + 3) & 31)];
    for (int k = threadIdx.x; k < DW; k += blockDim.x) {
        float e0 = embw[tok0 * DW + k];
        float e1 = embw[tok1 * DW + k];
        float e2 = embw[tok2 * DW + k];
        float e3 = embw[tok3 * DW + k];
        xs01[k] = pk2(e0, e1);
        xs23[k] = pk2(e2, e3);
    }
    __syncthreads();
    int j = threadIdx.x;
    float bj = bx[j];
    unsigned long long a01 = pk2(bj, bj), a23 = a01;
    float wv[10];
    #pragma unroll
    for (int i = 0; i < 10; i++) wv[i] = Wx[i * G3 + j];
    #pragma unroll 1
    for (int k0 = 0; k0 < DW; k0 += 10) {
        float wn[10];
        int kn = (k0 + 10 < DW) ? (k0 + 10) : k0;
        #pragma unroll
        for (int i = 0; i < 10; i++) wn[i] = Wx[(kn + i) * G3 + j];
        #pragma unroll
        for (int i = 0; i < 10; i++) {
            unsigned long long wd = pk2(wv[i], wv[i]);
            fma2(a01, xs01[k0 + i], wd, a01);
            fma2(a23, xs23[k0 + i], wd, a23);
        }
        #pragma unroll
        for (int i = 0; i < 10; i++) wv[i] = wn[i];
    }
    float2 f01 = upk2(a01), f23 = upk2(a23);
    g_gx[d][(bt0 + 0) >> 5][(bt0 + 0) & 31][j] = f01.x;
    g_gx[d][(bt0 + 1) >> 5][(bt0 + 1) & 31][j] = f01.y;
    g_gx[d][(bt0 + 2) >> 5][(bt0 + 2) & 31][j] = f23.x;
    g_gx[d][(bt0 + 3) >> 5][(bt0 + 3) & 31][j] = f23.y;
}

// GRU recurrence (r5 form — measured best). 2 blocks x 384 threads.
__global__ __launch_bounds__(G3, 1) void k_gru(const int* __restrict__ q,
                      const float* __restrict__ WhF, const float* __restrict__ bhF,
                      const float* __restrict__ WhB, const float* __restrict__ bhB) {
    extern __shared__ float sm[];
    float* gx_s = sm;                                       // [BB*TT*G3]
    ulonglong2* hs4 = (ulonglong2*)(sm + BB * TT * G3);     // [HD]
    float* gh = (float*)(hs4 + HD);                         // [BB*G3]
    int* msk = (int*)(gh + BB * G3);                        // [BB*TT]
    int d = blockIdx.x;
    const float* Wh = d ? WhB : WhF;
    const float* bh = d ? bhB : bhF;
    int tid = threadIdx.x;
    {
        const float4* src = (const float4*)&g_gx[d][0][0][0];
        float4* dst = (float4*)gx_s;
        #pragma unroll
        for (int i = 0; i < 32; i++) dst[i * G3 + tid] = src[i * G3 + tid];
    }
    if (tid < BB * TT) msk[tid] = (q[tid] != 0);
    if (tid < HD) hs4[tid] = make_ulonglong2(0ull, 0ull);
    float w[HD];
    #pragma unroll
    for (int k = 0; k < HD; k++) w[k] = Wh[k * G3 + tid];
    float bj = bh[tid];
    unsigned long long bj2 = pk2(bj, bj);
    __syncthreads();
    for (int s = 0; s < TT; s++) {
        int t = d ? (TT - 1 - s) : s;
        unsigned long long a01 = bj2, a23 = bj2;
        #pragma unroll
        for (int k = 0; k < HD; k++) {
            unsigned long long wd = pk2(w[k], w[k]);
            ulonglong2 hv = hs4[k];
            fma2(a01, hv.x, wd, a01);
            fma2(a23, hv.y, wd, a23);
        }
        float2 f01 = upk2(a01), f23 = upk2(a23);
        gh[0 * G3 + tid] = f01.x; gh[1 * G3 + tid] = f01.y;
        gh[2 * G3 + tid] = f23.x; gh[3 * G3 + tid] = f23.y;
        __syncthreads();
        for (int u = tid; u < BB * HD; u += G3) {
            int b = u >> 7, i = u & 127;
            const float* gx = &gx_s[(b * TT + t) * G3];
            float r = sigm(gx[i] + gh[b * G3 + i]);
            float z = sigm(gx[HD + i] + gh[b * G3 + HD + i]);
            float n = tanh_fast(gx[2 * HD + i] + r * gh[b * G3 + 2 * HD + i]);
            float hold = ((float*)hs4)[i * 4 + b];
            float hn = (1.f - z) * n + z * hold;
            if (msk[b * TT + t]) ((float*)hs4)[i * 4 + b] = hn;
        }
        __syncthreads();
    }
    for (int u = tid; u < BB * HD; u += G3) {
        int b = u >> 7, i = u & 127;
        g_qemb[b][d * HD + i] = ((float*)hs4)[i * 4 + b];
    }
}

// qg (block-redundant) + per-vocab scores S[v][b] = qg[b] . emb_desc[v].
__global__ void k_svqg(const float* __restrict__ embd,
                       const float* __restrict__ Whg, const float* __restrict__ bhg) {
    __shared__ float qs[BB][G];
    int tid = threadIdx.x;
    {
        int b = tid >> 6, g = tid & 63;
        float acc = bhg[g];
        #pragma unroll 8
        for (int k = 0; k < DH; k++) acc = fmaf(g_qemb[b][k], Whg[k * G + g], acc);
        qs[b][g] = acc;
        if (blockIdx.x == 0) g_qg[b][g] = acc;
    }
    __syncthreads();
    int v = blockIdx.x * 256 + tid;
    if (v >= VD) return;
    float s0 = 0.f, s1 = 0.f, s2 = 0.f, s3 = 0.f;
    const float4* row = (const float4*)&embd[v * G];
    #pragma unroll
    for (int g4 = 0; g4 < G / 4; g4++) {
        float4 e = row[g4];
        float4 q0 = *(float4*)&qs[0][g4 * 4];
        float4 q1 = *(float4*)&qs[1][g4 * 4];
        float4 q2 = *(float4*)&qs[2][g4 * 4];
        float4 q3 = *(float4*)&qs[3][g4 * 4];
        s0 += e.x * q0.x + e.y * q0.y + e.z * q0.z + e.w * q0.w;
        s1 += e.x * q1.x + e.y * q1.y + e.z * q1.z + e.w * q1.w;
        s2 += e.x * q2.x + e.y * q2.y + e.z * q2.z + e.w * q2.w;
        s3 += e.x * q3.x + e.y * q3.y + e.z * q3.z + e.w * q3.w;
    }
    g_S[v] = make_float4(s0, s1, s2, s3);
}

// desc attention -> nf0 (half2 out). Warp/node; scores via S-table lookup.
#define NFW 8
__global__ void k_nf0(const int* __restrict__ descs, const float* __restrict__ embd) {
    __shared__ float attnw[NFW][DL][BB];
    int tid = threadIdx.x, lane = tid & 31, wl = tid >> 5;
    int n = blockIdx.x * NFW + wl;
    int t16 = lane & 15, half = lane >> 4;
    int tok = descs[n * DL + t16];
    float4 sv = g_S[tok];
    float sa = half ? sv.y : sv.x;
    float sb = half ? sv.w : sv.z;
    float ma = sa, mb = sb;
    #pragma unroll
    for (int o = 1; o < 16; o <<= 1) {
        ma = fmaxf(ma, __shfl_xor_sync(0xFFFFFFFFu, ma, o));
        mb = fmaxf(mb, __shfl_xor_sync(0xFFFFFFFFu, mb, o));
    }
    float ea = __expf(sa - ma), eb = __expf(sb - mb);
    float da = ea, db = eb;
    #pragma unroll
    for (int o = 1; o < 16; o <<= 1) {
        da += __shfl_xor_sync(0xFFFFFFFFu, da, o);
        db += __shfl_xor_sync(0xFFFFFFFFu, db, o);
    }
    attnw[wl][t16][half]     = ea / da;
    attnw[wl][t16][2 + half] = eb / db;
    __syncwarp();
    float o00 = 0.f, o01 = 0.f, o10 = 0.f, o11 = 0.f;
    float o20 = 0.f, o21 = 0.f, o30 = 0.f, o31 = 0.f;
    #pragma unroll
    for (int t = 0; t < DL; t++) {
        int tk = __shfl_sync(0xFFFFFFFFu, tok, t);
        float2 x = *(const float2*)&embd[tk * G + 2 * lane];
        float4 w4 = *(float4*)&attnw[wl][t][0];
        o00 = fmaf(w4.x, x.x, o00); o01 = fmaf(w4.x, x.y, o01);
        o10 = fmaf(w4.y, x.x, o10); o11 = fmaf(w4.y, x.y, o11);
        o20 = fmaf(w4.z, x.x, o20); o21 = fmaf(w4.z, x.y, o21);
        o30 = fmaf(w4.w, x.x, o30); o31 = fmaf(w4.w, x.y, o31);
    }
    g_nf0h[n][0 * 32 + lane] = __floats2half2_rn(o00, o01);
    g_nf0h[n][1 * 32 + lane] = __floats2half2_rn(o10, o11);
    g_nf0h[n][2 * 32 + lane] = __floats2half2_rn(o20, o21);
    g_nf0h[n][3 * 32 + lane] = __floats2half2_rn(o30, o31);
}

__global__ void k_deg(const int* __restrict__ dst) {
    int e = blockIdx.x * blockDim.x + threadIdx.x;
    if (e < NE) atomicAdd(&g_deg[dst[e]], 1);
}

// single-block warp-shfl exclusive scan; re-zeroes g_deg for next replay
__global__ void k_scan() {
    __shared__ int wsum[32];
    __shared__ int carry;
    int tid = threadIdx.x, lane = tid & 31, wid = tid >> 5;
    if (tid == 0) carry = 0;
    __syncthreads();
    for (int base = 0; base < NN; base += 1024) {
        int idx = base + tid;
        int v = (idx < NN) ? g_deg[idx] : 0;
        if (idx < NN) g_deg[idx] = 0;
        int x = v;
        #pragma unroll
        for (int o = 1; o < 32; o <<= 1) {
            int y = __shfl_up_sync(0xFFFFFFFFu, x, o);
            if (lane >= o) x += y;
        }
        if (lane == 31) wsum[wid] = x;
        __syncthreads();
        if (wid == 0) {
            int s = wsum[lane];
            #pragma unroll
            for (int o = 1; o < 32; o <<= 1) {
                int y = __shfl_up_sync(0xFFFFFFFFu, s, o);
                if (lane >= o) s += y;
            }
            wsum[lane] = s;
        }
        __syncthreads();
        int ex = carry + (wid ? wsum[wid - 1] : 0) + x - v;
        if (idx < NN) { g_off[idx] = ex; g_cur[idx] = ex; }
        __syncthreads();
        if (tid == 0) carry += wsum[31];
        __syncthreads();
    }
    if (tid == 0) g_off[NN] = carry;
}

__global__ void k_perm(const int* __restrict__ src, const int* __restrict__ dst,
                       const int* __restrict__ et, const float* __restrict__ wcomp) {
    int e = blockIdx.x * blockDim.x + threadIdx.x;
    if (e >= NE) return;
    int pos = atomicAdd(&g_cur[dst[e]], 1);
    g_psrc[pos] = src[e];
    g_pw[pos]   = wcomp[et[e]];
}

// edge aggregation: 2 warps per dst node; 4-way batched edge loop for MLP.
__global__ void k_agg() {
    int gw = (blockIdx.x * blockDim.x + threadIdx.x) >> 5;
    int lane = threadIdx.x & 31;
    if (gw >= NN * 2) return;
    int n = gw >> 1, hb = gw & 1;
    int beg = g_off[n], end = g_off[n + 1];
    float a0 = 0.f, a1 = 0.f, a2 = 0.f, a3 = 0.f;
    int poff = hb * 64 + lane * 2;
    int i = beg;
    for (; i + 4 <= end; i += 4) {
        int s0 = g_psrc[i], s1 = g_psrc[i + 1], s2 = g_psrc[i + 2], s3 = g_psrc[i + 3];
        float w0 = g_pw[i], w1 = g_pw[i + 1], w2 = g_pw[i + 2], w3 = g_pw[i + 3];
        uint2 v0 = *(const uint2*)&g_nf0h[s0][poff];
        uint2 v1 = *(const uint2*)&g_nf0h[s1][poff];
        uint2 v2 = *(const uint2*)&g_nf0h[s2][poff];
        uint2 v3 = *(const uint2*)&g_nf0h[s3][poff];
        float2 f;
        f = __half22float2(*(__half2*)&v0.x); a0 = fmaf(w0, f.x, a0); a1 = fmaf(w0, f.y, a1);
        f = __half22float2(*(__half2*)&v0.y); a2 = fmaf(w0, f.x, a2); a3 = fmaf(w0, f.y, a3);
        f = __half22float2(*(__half2*)&v1.x); a0 = fmaf(w1, f.x, a0); a1 = fmaf(w1, f.y, a1);
        f = __half22float2(*(__half2*)&v1.y); a2 = fmaf(w1, f.x, a2); a3 = fmaf(w1, f.y, a3);
        f = __half22float2(*(__half2*)&v2.x); a0 = fmaf(w2, f.x, a0); a1 = fmaf(w2, f.y, a1);
        f = __half22float2(*(__half2*)&v2.y); a2 = fmaf(w2, f.x, a2); a3 = fmaf(w2, f.y, a3);
        f = __half22float2(*(__half2*)&v3.x); a0 = fmaf(w3, f.x, a0); a1 = fmaf(w3, f.y, a1);
        f = __half22float2(*(__half2*)&v3.y); a2 = fmaf(w3, f.x, a2); a3 = fmaf(w3, f.y, a3);
    }
    for (; i < end; i++) {
        int s = g_psrc[i];
        float w = g_pw[i];
        uint2 v = *(const uint2*)&g_nf0h[s][poff];
        float2 f0 = __half22float2(*(__half2*)&v.x), f1 = __half22float2(*(__half2*)&v.y);
        a0 = fmaf(w, f0.x, a0); a1 = fmaf(w, f0.y, a1);
        a2 = fmaf(w, f1.x, a2); a3 = fmaf(w, f1.y, a3);
    }
    *(float4*)&g_sacc[n][hb * 128 + lane * 4] = make_float4(a0, a1, a2, a3);
}

// nf1 = relu(s @ bases + bias) fused with ONLINE-SOFTMAX attention pooling.
// Software-pipelined: next node's row prefetched into regs during compute.
__global__ void k_rgcn(const float* __restrict__ bases, const float* __restrict__ bias) {
    __shared__ float bs[G * G];
    __shared__ float srow[BG];
    __shared__ float swred[8];
    __shared__ float sv_s[BB];
    int tid = threadIdx.x;   // 256
    for (int i = tid; i < G * G; i += 256) bs[i] = bases[i];
    int b = tid >> 6, g = tid & 63;
    float bia = bias[g];
    float qv = g_qg[b][g];
    float m_run = -3.0e38f, den = 0.f, aggr = 0.f;
    float cur = g_sacc[blockIdx.x][tid];
    __syncthreads();
    for (int n = blockIdx.x; n < NN; n += RB) {
        srow[tid] = cur;
        __syncthreads();
        int nn = n + RB;
        float nxt = (nn < NN) ? g_sacc[nn][tid] : 0.f;   // prefetch, hidden by dot
        float acc = bia;
        const float* sb = &srow[b * G];
        #pragma unroll 8
        for (int k = 0; k < G; k++) acc = fmaf(sb[k], bs[k * G + g], acc);
        acc = fmaxf(acc, 0.f);
        float p = acc * qv;
        p += __shfl_xor_sync(0xFFFFFFFFu, p, 16);
        p += __shfl_xor_sync(0xFFFFFFFFu, p, 8);
        p += __shfl_xor_sync(0xFFFFFFFFu, p, 4);
        p += __shfl_xor_sync(0xFFFFFFFFu, p, 2);
        p += __shfl_xor_sync(0xFFFFFFFFu, p, 1);
        if ((tid & 31) == 0) swred[tid >> 5] = p;
        __syncthreads();
        if (tid < BB) sv_s[tid] = swred[2 * tid] + swred[2 * tid + 1];
        __syncthreads();
        float sv = sv_s[b];
        float m_new = fmaxf(m_run, sv);
        float sc = __expf(m_run - m_new);
        float e = __expf(sv - m_new);
        aggr = aggr * sc + e * acc;
        den  = den * sc + e;
        m_run = m_new;
        cur = nxt;
    }
    g_pagg[blockIdx.x][b][g] = aggr;
    if (g == 0) { g_pden[blockIdx.x][b] = den; g_pm[blockIdx.x][b] = m_run; }
}

// hidden partials, q_emb-only part (kp=1..3): 24 blocks x 128. Dep: gru only.
__global__ void k_hiddenQ(const float* __restrict__ W1) {
    int hb = blockIdx.x / 3, kp = 1 + blockIdx.x % 3;
    int tid = threadIdx.x;
    int h = hb * 128 + tid;
    int k0 = kp * 80;
    __shared__ float feat[BB][80];
    for (int i = tid; i < BB * 80; i += 128) {
        int b = i / 80, kk = i % 80;
        feat[b][kk] = g_qemb[b][k0 + kk - G];
    }
    __syncthreads();
    float a0 = 0.f, a1 = 0.f, a2 = 0.f, a3 = 0.f;
    #pragma unroll 4
    for (int kk = 0; kk < 80; kk++) {
        float w = W1[(k0 + kk) * H1 + h];
        a0 = fmaf(feat[0][kk], w, a0);
        a1 = fmaf(feat[1][kk], w, a1);
        a2 = fmaf(feat[2][kk], w, a2);
        a3 = fmaf(feat[3][kk], w, a3);
    }
    g_hidp[kp][0][h] = a0; g_hidp[kp][1][h] = a1;
    g_hidp[kp][2][h] = a2; g_hidp[kp][3][h] = a3;
}

// hidden partials, pool part (kp=0): 8 blocks x 128; fuses softmax combine.
__global__ void k_hiddenP(const float* __restrict__ W1) {
    int hb = blockIdx.x;
    int tid = threadIdx.x;
    int h = hb * 128 + tid;
    __shared__ float feat[BB][80];
    for (int i = tid; i < BB * 80; i += 128) {
        int b = i / 80, kk = i % 80;
        if (kk < G) {
            float m = -3.0e38f;
            #pragma unroll 4
            for (int r = 0; r < RB; r++) m = fmaxf(m, g_pm[r][b]);
            float acc = 0.f, den = 0.f;
            #pragma unroll 4
            for (int r = 0; r < RB; r++) {
                float sc = __expf(g_pm[r][b] - m);
                acc = fmaf(g_pagg[r][b][kk], sc, acc);
                den = fmaf(g_pden[r][b], sc, den);
            }
            feat[b][kk] = acc / den;
        } else {
            feat[b][kk] = g_qemb[b][kk - G];
        }
    }
    __syncthreads();
    float a0 = 0.f, a1 = 0.f, a2 = 0.f, a3 = 0.f;
    #pragma unroll 4
    for (int kk = 0; kk < 80; kk++) {
        float w = W1[kk * H1 + h];
        a0 = fmaf(feat[0][kk], w, a0);
        a1 = fmaf(feat[1][kk], w, a1);
        a2 = fmaf(feat[2][kk], w, a2);
        a3 = fmaf(feat[3][kk], w, a3);
    }
    g_hidp[0][0][h] = a0; g_hidp[0][1][h] = a1;
    g_hidp[0][2][h] = a2; g_hidp[0][3][h] = a3;
}

// logits: 63 blocks x 512 (16 k-parts x 32 classes); relu+bias fused.
__global__ void k_logits(const float* __restrict__ W2, const float* __restrict__ b1,
                         const float* __restrict__ b2, float* __restrict__ out) {
    __shared__ float hsm[BB][H1];
    __shared__ float red[16][32][BB];
    int tid = threadIdx.x;
    for (int i = tid; i < BB * H1; i += 512) {
        int b = i >> 10, k = i & (H1 - 1);
        float v = g_hidp[0][b][k] + g_hidp[1][b][k] + g_hidp[2][b][k] + g_hidp[3][b][k] + b1[k];
        hsm[b][k] = fmaxf(v, 0.f);
    }
    __syncthreads();
    int kp = tid >> 5, cl = tid & 31;
    int c = blockIdx.x * 32 + cl;
    float a0 = 0.f, a1 = 0.f, a2 = 0.f, a3 = 0.f;
    if (c < NC) {
        int k0 = kp * 64;
        #pragma unroll 4
        for (int k = k0; k < k0 + 64; k++) {
            float w = W2[k * NC + c];
            a0 = fmaf(hsm[0][k], w, a0);
            a1 = fmaf(hsm[1][k], w, a1);
            a2 = fmaf(hsm[2][k], w, a2);
            a3 = fmaf(hsm[3][k], w, a3);
        }
    }
    red[kp][cl][0] = a0; red[kp][cl][1] = a1; red[kp][cl][2] = a2; red[kp][cl][3] = a3;
    __syncthreads();
    if (kp == 0 && c < NC) {
        float bb2 = b2[c];
        #pragma unroll
        for (int b = 0; b < BB; b++) {
            float s = bb2;
            #pragma unroll
            for (int p = 0; p < 16; p++) s += red[p][cl][b];
            out[b * NC + c] = s;
        }
    }
}

// ---------------- launch ----------------
extern "C" void kernel_launch(void* const* d_in, const int* in_sizes, int n_in,
                              void* d_out, int out_size) {
    const int*   questions = (const int*)d_in[0];
    const int*   node_descs= (const int*)d_in[1];
    const int*   edge_src  = (const int*)d_in[2];
    const int*   edge_dst  = (const int*)d_in[3];
    const int*   edge_type = (const int*)d_in[4];
    const float* emb_word  = (const float*)d_in[5];
    const float* emb_desc  = (const float*)d_in[6];
    const float* Wx_f = (const float*)d_in[7];
    const float* Wh_f = (const float*)d_in[8];
    const float* bx_f = (const float*)d_in[9];
    const float* bh_f = (const float*)d_in[10];
    const float* Wx_b = (const float*)d_in[11];
    const float* Wh_b = (const float*)d_in[12];
    const float* bx_b = (const float*)d_in[13];
    const float* bh_b = (const float*)d_in[14];
    const float* W_hg = (const float*)d_in[15];
    const float* b_hg = (const float*)d_in[16];
    const float* bases = (const float*)d_in[17];
    const float* w_comp = (const float*)d_in[18];
    const float* rgcn_bias = (const float*)d_in[19];
    const float* W1 = (const float*)d_in[20];
    const float* b1 = (const float*)d_in[21];
    const float* W2 = (const float*)d_in[22];
    const float* b2 = (const float*)d_in[23];
    float* out = (float*)d_out;

    static cudaStream_t s1 = nullptr;
    static cudaEvent_t ev0 = nullptr, ev1 = nullptr, ev2 = nullptr, ev3 = nullptr;
    if (!s1) {
        cudaStreamCreateWithFlags(&s1, cudaStreamNonBlocking);
        cudaEventCreateWithFlags(&ev0, cudaEventDisableTiming);
        cudaEventCreateWithFlags(&ev1, cudaEventDisableTiming);
        cudaEventCreateWithFlags(&ev2, cudaEventDisableTiming);
        cudaEventCreateWithFlags(&ev3, cudaEventDisableTiming);
        cudaFuncSetAttribute(k_gru, cudaFuncAttributeMaxDynamicSharedMemorySize, SMEM_GRU);
    }

    cudaEventRecord(ev0, 0);
    cudaStreamWaitEvent(s1, ev0, 0);

    k_deg<<<(NE + 255) / 256, 256, 0, s1>>>(edge_dst);                     // 1 (s1)
    k_scan<<<1, 1024, 0, s1>>>();                                          // 2 (s1)
    k_gx<<<64, G3>>>(questions, emb_word, Wx_f, bx_f, Wx_b, bx_b);        // 3
    k_gru<<<2, G3, SMEM_GRU>>>(questions, Wh_f, bh_f, Wh_b, bh_b);        // 4 (ncu slot)
    cudaEventRecord(ev2, 0);
    k_perm<<<(NE + 255) / 256, 256, 0, s1>>>(edge_src, edge_dst, edge_type, w_comp); // 5 (s1)
    cudaEventRecord(ev1, s1);
    cudaStreamWaitEvent(s1, ev2, 0);
    k_hiddenQ<<<24, 128, 0, s1>>>(W1);                                     // 6 (s1, overlaps)
    cudaEventRecord(ev3, s1);
    k_svqg<<<(VD + 255) / 256, 256>>>(emb_desc, W_hg, b_hg);               // 7
    k_nf0<<<NN / NFW, 256>>>(node_descs, emb_desc);                        // 8
    cudaStreamWaitEvent(0, ev1, 0);
    k_agg<<<(NN * 2 * 32 + 255) / 256, 256>>>();                           // 9
    k_rgcn<<<RB, 256>>>(bases, rgcn_bias);                                 // 10
    k_hiddenP<<<8, 128>>>(W1);                                             // 11
    cudaStreamWaitEvent(0, ev3, 0);
    k_logits<<<63, 512>>>(W2, b1, b2, out);                                // 12
}

// round 15
// speedup vs baseline: 1.2587x; 1.2397x over previous
#include <cuda_runtime.h>
#include <cuda_fp16.h>
#include <math.h>

#define NN 20000
#define NE 320000
#define NR 200
#define DL 16
#define G  64
#define DW 300
#define DH 256
#define HD 128
#define NC 2000
#define VD 30000
#define BB 4
#define TT 32
#define G3 (3*HD)    // 384
#define BG (BB*G)    // 256
#define H1 1024
#define FEAT (G+DH)  // 320
#define RB 296       // rgcn blocks

// k_gru dyn smem (per (dir,batch) block): gx[TT*G3] + h[HD] + gh[G3] + msk[TT]
#define SMEM_GRU (TT*G3*4 + HD*4 + G3*4 + TT*4)   // 51328

// ---------------- scratch ----------------
__device__ float g_gx[2][BB][TT][G3];
__device__ float g_qemb[BB][DH];
__device__ float g_qg[BB][G];
__device__ float4 g_S[VD];           // per-vocab attention scores (b0..b3)
__device__ __half2 g_nf0h[NN][BG/2];
__device__ float g_sacc[NN][BG];
__device__ int   g_deg[NN];          // statically zero; re-zeroed by k_scan
__device__ int   g_off[NN+1];
__device__ int   g_cur[NN];
__device__ int   g_psrc[NE];
__device__ float g_pw[NE];
__device__ float g_pm[RB][BB];       // per-block softmax max
__device__ float g_pden[RB][BB];     // per-block softmax denom
__device__ float g_pagg[RB][BB][G];  // per-block weighted agg
__device__ float g_hidp[4][BB][H1];

// ---------------- helpers ----------------
__device__ __forceinline__ float sigm(float x) { return 1.f / (1.f + __expf(-x)); }
__device__ __forceinline__ float tanh_fast(float x) { return 2.f / (1.f + __expf(-2.f * x)) - 1.f; }

__device__ __forceinline__ void fma2(unsigned long long& d, unsigned long long a,
                                     unsigned long long b, unsigned long long c) {
    asm("fma.rn.f32x2 %0, %1, %2, %3;" : "=l"(d) : "l"(a), "l"(b), "l"(c));
}
__device__ __forceinline__ unsigned long long pk2(float x, float y) {
    unsigned long long r; asm("mov.b64 %0, {%1, %2};" : "=l"(r) : "f"(x), "f"(y)); return r;
}
__device__ __forceinline__ float2 upk2(unsigned long long v) {
    float2 f; asm("mov.b64 {%0, %1}, %2;" : "=f"(f.x), "=f"(f.y) : "l"(v)); return f;
}

// ---------------- kernels ----------------

// input gates gx = x @ Wx + bx.  64 blocks x 384 threads; double-buffered Wx loads.
__global__ __launch_bounds__(G3) void k_gx(const int* __restrict__ q,
                     const float* __restrict__ embw,
                     const float* __restrict__ WxF, const float* __restrict__ bxF,
                     const float* __restrict__ WxB, const float* __restrict__ bxB) {
    int d = blockIdx.x >> 5;
    int grp = blockIdx.x & 31;
    const float* Wx = d ? WxB : WxF;
    const float* bx = d ? bxB : bxF;
    __shared__ unsigned long long xs01[DW];
    __shared__ unsigned long long xs23[DW];
    int bt0 = grp * 4;
    int tok0 = q[((bt0 + 0) >> 5) * TT + ((bt0 + 0) & 31)];
    int tok1 = q[((bt0 + 1) >> 5) * TT + ((bt0 + 1) & 31)];
    int tok2 = q[((bt0 + 2) >> 5) * TT + ((bt0 + 2) & 31)];
    int tok3 = q[((bt0 + 3) >> 5) * TT + ((bt0 + 3) & 31)];
    for (int k = threadIdx.x; k < DW; k += blockDim.x) {
        float e0 = embw[tok0 * DW + k];
        float e1 = embw[tok1 * DW + k];
        float e2 = embw[tok2 * DW + k];
        float e3 = embw[tok3 * DW + k];
        xs01[k] = pk2(e0, e1);
        xs23[k] = pk2(e2, e3);
    }
    __syncthreads();
    int j = threadIdx.x;
    float bj = bx[j];
    unsigned long long a01 = pk2(bj, bj), a23 = a01;
    float wv[10];
    #pragma unroll
    for (int i = 0; i < 10; i++) wv[i] = Wx[i * G3 + j];
    #pragma unroll 1
    for (int k0 = 0; k0 < DW; k0 += 10) {
        float wn[10];
        int kn = (k0 + 10 < DW) ? (k0 + 10) : k0;
        #pragma unroll
        for (int i = 0; i < 10; i++) wn[i] = Wx[(kn + i) * G3 + j];
        #pragma unroll
        for (int i = 0; i < 10; i++) {
            unsigned long long wd = pk2(wv[i], wv[i]);
            fma2(a01, xs01[k0 + i], wd, a01);
            fma2(a23, xs23[k0 + i], wd, a23);
        }
        #pragma unroll
        for (int i = 0; i < 10; i++) wv[i] = wn[i];
    }
    float2 f01 = upk2(a01), f23 = upk2(a23);
    g_gx[d][(bt0 + 0) >> 5][(bt0 + 0) & 31][j] = f01.x;
    g_gx[d][(bt0 + 1) >> 5][(bt0 + 1) & 31][j] = f01.y;
    g_gx[d][(bt0 + 2) >> 5][(bt0 + 2) & 31][j] = f23.x;
    g_gx[d][(bt0 + 3) >> 5][(bt0 + 3) & 31][j] = f23.y;
}

// GRU recurrence. 8 blocks = (2 dirs x 4 batches) x 384 threads.
// Each (dir,batch) is an INDEPENDENT recurrence: thread j owns one output
// column with w[128] in regs and a single scalar FMA chain per step.
__global__ __launch_bounds__(G3, 1) void k_gru(const int* __restrict__ q,
                      const float* __restrict__ WhF, const float* __restrict__ bhF,
                      const float* __restrict__ WhB, const float* __restrict__ bhB) {
    extern __shared__ float sm[];
    float* gx_s = sm;                 // [TT*G3]
    float* h_s  = sm + TT * G3;       // [HD]
    float* gh   = h_s + HD;           // [G3]
    int*   msk  = (int*)(gh + G3);    // [TT]
    int d = blockIdx.x >> 2, b = blockIdx.x & 3;
    const float* Wh = d ? WhB : WhF;
    const float* bh = d ? bhB : bhF;
    int tid = threadIdx.x;
    {
        const float4* src = (const float4*)&g_gx[d][b][0][0];
        float4* dst = (float4*)gx_s;
        #pragma unroll
        for (int i = 0; i < 8; i++) dst[i * G3 + tid] = src[i * G3 + tid];
    }
    if (tid < TT) msk[tid] = (q[b * TT + tid] != 0);
    if (tid < HD) h_s[tid] = 0.f;
    float w[HD];
    #pragma unroll
    for (int k = 0; k < HD; k++) w[k] = Wh[k * G3 + tid];
    float bj = bh[tid];
    __syncthreads();
    for (int s = 0; s < TT; s++) {
        int t = d ? (TT - 1 - s) : s;
        float acc = bj;
        #pragma unroll
        for (int k = 0; k < HD; k++) acc = fmaf(h_s[k], w[k], acc);
        gh[tid] = acc;
        __syncthreads();
        if (tid < HD) {
            const float* gx = &gx_s[t * G3];
            int i = tid;
            float r = sigm(gx[i] + gh[i]);
            float z = sigm(gx[HD + i] + gh[HD + i]);
            float n = tanh_fast(gx[2 * HD + i] + r * gh[2 * HD + i]);
            float hn = (1.f - z) * n + z * h_s[i];
            if (msk[t]) h_s[i] = hn;
        }
        __syncthreads();
    }
    if (tid < HD) g_qemb[b][d * HD + tid] = h_s[tid];
}

// qg (block-redundant) + per-vocab scores S[v][b] = qg[b] . emb_desc[v].
__global__ void k_svqg(const float* __restrict__ embd,
                       const float* __restrict__ Whg, const float* __restrict__ bhg) {
    __shared__ float qs[BB][G];
    int tid = threadIdx.x;
    {
        int b = tid >> 6, g = tid & 63;
        float acc = bhg[g];
        #pragma unroll 8
        for (int k = 0; k < DH; k++) acc = fmaf(g_qemb[b][k], Whg[k * G + g], acc);
        qs[b][g] = acc;
        if (blockIdx.x == 0) g_qg[b][g] = acc;
    }
    __syncthreads();
    int v = blockIdx.x * 256 + tid;
    if (v >= VD) return;
    float s0 = 0.f, s1 = 0.f, s2 = 0.f, s3 = 0.f;
    const float4* row = (const float4*)&embd[v * G];
    #pragma unroll
    for (int g4 = 0; g4 < G / 4; g4++) {
        float4 e = row[g4];
        float4 q0 = *(float4*)&qs[0][g4 * 4];
        float4 q1 = *(float4*)&qs[1][g4 * 4];
        float4 q2 = *(float4*)&qs[2][g4 * 4];
        float4 q3 = *(float4*)&qs[3][g4 * 4];
        s0 += e.x * q0.x + e.y * q0.y + e.z * q0.z + e.w * q0.w;
        s1 += e.x * q1.x + e.y * q1.y + e.z * q1.z + e.w * q1.w;
        s2 += e.x * q2.x + e.y * q2.y + e.z * q2.z + e.w * q2.w;
        s3 += e.x * q3.x + e.y * q3.y + e.z * q3.z + e.w * q3.w;
    }
    g_S[v] = make_float4(s0, s1, s2, s3);
}

// desc attention -> nf0 (half2 out). Warp/node; scores via S-table lookup.
#define NFW 8
__global__ void k_nf0(const int* __restrict__ descs, const float* __restrict__ embd) {
    __shared__ float attnw[NFW][DL][BB];
    int tid = threadIdx.x, lane = tid & 31, wl = tid >> 5;
    int n = blockIdx.x * NFW + wl;
    int t16 = lane & 15, half = lane >> 4;
    int tok = descs[n * DL + t16];
    float4 sv = g_S[tok];
    float sa = half ? sv.y : sv.x;
    float sb = half ? sv.w : sv.z;
    float ma = sa, mb = sb;
    #pragma unroll
    for (int o = 1; o < 16; o <<= 1) {
        ma = fmaxf(ma, __shfl_xor_sync(0xFFFFFFFFu, ma, o));
        mb = fmaxf(mb, __shfl_xor_sync(0xFFFFFFFFu, mb, o));
    }
    float ea = __expf(sa - ma), eb = __expf(sb - mb);
    float da = ea, db = eb;
    #pragma unroll
    for (int o = 1; o < 16; o <<= 1) {
        da += __shfl_xor_sync(0xFFFFFFFFu, da, o);
        db += __shfl_xor_sync(0xFFFFFFFFu, db, o);
    }
    attnw[wl][t16][half]     = ea / da;
    attnw[wl][t16][2 + half] = eb / db;
    __syncwarp();
    float o00 = 0.f, o01 = 0.f, o10 = 0.f, o11 = 0.f;
    float o20 = 0.f, o21 = 0.f, o30 = 0.f, o31 = 0.f;
    #pragma unroll
    for (int t = 0; t < DL; t++) {
        int tk = __shfl_sync(0xFFFFFFFFu, tok, t);
        float2 x = *(const float2*)&embd[tk * G + 2 * lane];
        float4 w4 = *(float4*)&attnw[wl][t][0];
        o00 = fmaf(w4.x, x.x, o00); o01 = fmaf(w4.x, x.y, o01);
        o10 = fmaf(w4.y, x.x, o10); o11 = fmaf(w4.y, x.y, o11);
        o20 = fmaf(w4.z, x.x, o20); o21 = fmaf(w4.z, x.y, o21);
        o30 = fmaf(w4.w, x.x, o30); o31 = fmaf(w4.w, x.y, o31);
    }
    g_nf0h[n][0 * 32 + lane] = __floats2half2_rn(o00, o01);
    g_nf0h[n][1 * 32 + lane] = __floats2half2_rn(o10, o11);
    g_nf0h[n][2 * 32 + lane] = __floats2half2_rn(o20, o21);
    g_nf0h[n][3 * 32 + lane] = __floats2half2_rn(o30, o31);
}

__global__ void k_deg(const int* __restrict__ dst) {
    int e = blockIdx.x * blockDim.x + threadIdx.x;
    if (e < NE) atomicAdd(&g_deg[dst[e]], 1);
}

// single-block warp-shfl exclusive scan; re-zeroes g_deg for next replay
__global__ void k_scan() {
    __shared__ int wsum[32];
    __shared__ int carry;
    int tid = threadIdx.x, lane = tid & 31, wid = tid >> 5;
    if (tid == 0) carry = 0;
    __syncthreads();
    for (int base = 0; base < NN; base += 1024) {
        int idx = base + tid;
        int v = (idx < NN) ? g_deg[idx] : 0;
        if (idx < NN) g_deg[idx] = 0;
        int x = v;
        #pragma unroll
        for (int o = 1; o < 32; o <<= 1) {
            int y = __shfl_up_sync(0xFFFFFFFFu, x, o);
            if (lane >= o) x += y;
        }
        if (lane == 31) wsum[wid] = x;
        __syncthreads();
        if (wid == 0) {
            int s = wsum[lane];
            #pragma unroll
            for (int o = 1; o < 32; o <<= 1) {
                int y = __shfl_up_sync(0xFFFFFFFFu, s, o);
                if (lane >= o) s += y;
            }
            wsum[lane] = s;
        }
        __syncthreads();
        int ex = carry + (wid ? wsum[wid - 1] : 0) + x - v;
        if (idx < NN) { g_off[idx] = ex; g_cur[idx] = ex; }
        __syncthreads();
        if (tid == 0) carry += wsum[31];
        __syncthreads();
    }
    if (tid == 0) g_off[NN] = carry;
}

__global__ void k_perm(const int* __restrict__ src, const int* __restrict__ dst,
                       const int* __restrict__ et, const float* __restrict__ wcomp) {
    int e = blockIdx.x * blockDim.x + threadIdx.x;
    if (e >= NE) return;
    int pos = atomicAdd(&g_cur[dst[e]], 1);
    g_psrc[pos] = src[e];
    g_pw[pos]   = wcomp[et[e]];
}

// edge aggregation: 2 warps per dst node; 4-way batched edge loop for MLP.
__global__ void k_agg() {
    int gw = (blockIdx.x * blockDim.x + threadIdx.x) >> 5;
    int lane = threadIdx.x & 31;
    if (gw >= NN * 2) return;
    int n = gw >> 1, hb = gw & 1;
    int beg = g_off[n], end = g_off[n + 1];
    float a0 = 0.f, a1 = 0.f, a2 = 0.f, a3 = 0.f;
    int poff = hb * 64 + lane * 2;
    int i = beg;
    for (; i + 4 <= end; i += 4) {
        int s0 = g_psrc[i], s1 = g_psrc[i + 1], s2 = g_psrc[i + 2], s3 = g_psrc[i + 3];
        float w0 = g_pw[i], w1 = g_pw[i + 1], w2 = g_pw[i + 2], w3 = g_pw[i + 3];
        uint2 v0 = *(const uint2*)&g_nf0h[s0][poff];
        uint2 v1 = *(const uint2*)&g_nf0h[s1][poff];
        uint2 v2 = *(const uint2*)&g_nf0h[s2][poff];
        uint2 v3 = *(const uint2*)&g_nf0h[s3][poff];
        float2 f;
        f = __half22float2(*(__half2*)&v0.x); a0 = fmaf(w0, f.x, a0); a1 = fmaf(w0, f.y, a1);
        f = __half22float2(*(__half2*)&v0.y); a2 = fmaf(w0, f.x, a2); a3 = fmaf(w0, f.y, a3);
        f = __half22float2(*(__half2*)&v1.x); a0 = fmaf(w1, f.x, a0); a1 = fmaf(w1, f.y, a1);
        f = __half22float2(*(__half2*)&v1.y); a2 = fmaf(w1, f.x, a2); a3 = fmaf(w1, f.y, a3);
        f = __half22float2(*(__half2*)&v2.x); a0 = fmaf(w2, f.x, a0); a1 = fmaf(w2, f.y, a1);
        f = __half22float2(*(__half2*)&v2.y); a2 = fmaf(w2, f.x, a2); a3 = fmaf(w2, f.y, a3);
        f = __half22float2(*(__half2*)&v3.x); a0 = fmaf(w3, f.x, a0); a1 = fmaf(w3, f.y, a1);
        f = __half22float2(*(__half2*)&v3.y); a2 = fmaf(w3, f.x, a2); a3 = fmaf(w3, f.y, a3);
    }
    for (; i < end; i++) {
        int s = g_psrc[i];
        float w = g_pw[i];
        uint2 v = *(const uint2*)&g_nf0h[s][poff];
        float2 f0 = __half22float2(*(__half2*)&v.x), f1 = __half22float2(*(__half2*)&v.y);
        a0 = fmaf(w, f0.x, a0); a1 = fmaf(w, f0.y, a1);
        a2 = fmaf(w, f1.x, a2); a3 = fmaf(w, f1.y, a3);
    }
    *(float4*)&g_sacc[n][hb * 128 + lane * 4] = make_float4(a0, a1, a2, a3);
}

// nf1 = relu(s @ bases + bias) fused with ONLINE-SOFTMAX attention pooling.
__global__ void k_rgcn(const float* __restrict__ bases, const float* __restrict__ bias) {
    __shared__ float bs[G * G];
    __shared__ float srow[BG];
    __shared__ float swred[8];
    __shared__ float sv_s[BB];
    int tid = threadIdx.x;   // 256
    for (int i = tid; i < G * G; i += 256) bs[i] = bases[i];
    int b = tid >> 6, g = tid & 63;
    float bia = bias[g];
    float qv = g_qg[b][g];
    float m_run = -3.0e38f, den = 0.f, aggr = 0.f;
    float cur = g_sacc[blockIdx.x][tid];
    __syncthreads();
    for (int n = blockIdx.x; n < NN; n += RB) {
        srow[tid] = cur;
        __syncthreads();
        int nn = n + RB;
        float nxt = (nn < NN) ? g_sacc[nn][tid] : 0.f;
        float acc = bia;
        const float* sb = &srow[b * G];
        #pragma unroll 8
        for (int k = 0; k < G; k++) acc = fmaf(sb[k], bs[k * G + g], acc);
        acc = fmaxf(acc, 0.f);
        float p = acc * qv;
        p += __shfl_xor_sync(0xFFFFFFFFu, p, 16);
        p += __shfl_xor_sync(0xFFFFFFFFu, p, 8);
        p += __shfl_xor_sync(0xFFFFFFFFu, p, 4);
        p += __shfl_xor_sync(0xFFFFFFFFu, p, 2);
        p += __shfl_xor_sync(0xFFFFFFFFu, p, 1);
        if ((tid & 31) == 0) swred[tid >> 5] = p;
        __syncthreads();
        if (tid < BB) sv_s[tid] = swred[2 * tid] + swred[2 * tid + 1];
        __syncthreads();
        float sv = sv_s[b];
        float m_new = fmaxf(m_run, sv);
        float sc = __expf(m_run - m_new);
        float e = __expf(sv - m_new);
        aggr = aggr * sc + e * acc;
        den  = den * sc + e;
        m_run = m_new;
        cur = nxt;
    }
    g_pagg[blockIdx.x][b][g] = aggr;
    if (g == 0) { g_pden[blockIdx.x][b] = den; g_pm[blockIdx.x][b] = m_run; }
}

// hidden partials, q_emb-only part (kp=1..3): 24 blocks x 128. Dep: gru only.
__global__ void k_hiddenQ(const float* __restrict__ W1) {
    int hb = blockIdx.x / 3, kp = 1 + blockIdx.x % 3;
    int tid = threadIdx.x;
    int h = hb * 128 + tid;
    int k0 = kp * 80;
    __shared__ float feat[BB][80];
    for (int i = tid; i < BB * 80; i += 128) {
        int b = i / 80, kk = i % 80;
        feat[b][kk] = g_qemb[b][k0 + kk - G];
    }
    __syncthreads();
    float a0 = 0.f, a1 = 0.f, a2 = 0.f, a3 = 0.f;
    #pragma unroll 4
    for (int kk = 0; kk < 80; kk++) {
        float w = W1[(k0 + kk) * H1 + h];
        a0 = fmaf(feat[0][kk], w, a0);
        a1 = fmaf(feat[1][kk], w, a1);
        a2 = fmaf(feat[2][kk], w, a2);
        a3 = fmaf(feat[3][kk], w, a3);
    }
    g_hidp[kp][0][h] = a0; g_hidp[kp][1][h] = a1;
    g_hidp[kp][2][h] = a2; g_hidp[kp][3][h] = a3;
}

// hidden partials, pool part (kp=0): 8 blocks x 128; fuses softmax combine.
__global__ void k_hiddenP(const float* __restrict__ W1) {
    int hb = blockIdx.x;
    int tid = threadIdx.x;
    int h = hb * 128 + tid;
    __shared__ float feat[BB][80];
    for (int i = tid; i < BB * 80; i += 128) {
        int b = i / 80, kk = i % 80;
        if (kk < G) {
            float m = -3.0e38f;
            #pragma unroll 4
            for (int r = 0; r < RB; r++) m = fmaxf(m, g_pm[r][b]);
            float acc = 0.f, den = 0.f;
            #pragma unroll 4
            for (int r = 0; r < RB; r++) {
                float sc = __expf(g_pm[r][b] - m);
                acc = fmaf(g_pagg[r][b][kk], sc, acc);
                den = fmaf(g_pden[r][b], sc, den);
            }
            feat[b][kk] = acc / den;
        } else {
            feat[b][kk] = g_qemb[b][kk - G];
        }
    }
    __syncthreads();
    float a0 = 0.f, a1 = 0.f, a2 = 0.f, a3 = 0.f;
    #pragma unroll 4
    for (int kk = 0; kk < 80; kk++) {
        float w = W1[kk * H1 + h];
        a0 = fmaf(feat[0][kk], w, a0);
        a1 = fmaf(feat[1][kk], w, a1);
        a2 = fmaf(feat[2][kk], w, a2);
        a3 = fmaf(feat[3][kk], w, a3);
    }
    g_hidp[0][0][h] = a0; g_hidp[0][1][h] = a1;
    g_hidp[0][2][h] = a2; g_hidp[0][3][h] = a3;
}

// logits: 63 blocks x 512 (16 k-parts x 32 classes); relu+bias fused.
__global__ void k_logits(const float* __restrict__ W2, const float* __restrict__ b1,
                         const float* __restrict__ b2, float* __restrict__ out) {
    __shared__ float hsm[BB][H1];
    __shared__ float red[16][32][BB];
    int tid = threadIdx.x;
    for (int i = tid; i < BB * H1; i += 512) {
        int b = i >> 10, k = i & (H1 - 1);
        float v = g_hidp[0][b][k] + g_hidp[1][b][k] + g_hidp[2][b][k] + g_hidp[3][b][k] + b1[k];
        hsm[b][k] = fmaxf(v, 0.f);
    }
    __syncthreads();
    int kp = tid >> 5, cl = tid & 31;
    int c = blockIdx.x * 32 + cl;
    float a0 = 0.f, a1 = 0.f, a2 = 0.f, a3 = 0.f;
    if (c < NC) {
        int k0 = kp * 64;
        #pragma unroll 4
        for (int k = k0; k < k0 + 64; k++) {
            float w = W2[k * NC + c];
            a0 = fmaf(hsm[0][k], w, a0);
            a1 = fmaf(hsm[1][k], w, a1);
            a2 = fmaf(hsm[2][k], w, a2);
            a3 = fmaf(hsm[3][k], w, a3);
        }
    }
    red[kp][cl][0] = a0; red[kp][cl][1] = a1; red[kp][cl][2] = a2; red[kp][cl][3] = a3;
    __syncthreads();
    if (kp == 0 && c < NC) {
        float bb2 = b2[c];
        #pragma unroll
        for (int b = 0; b < BB; b++) {
            float s = bb2;
            #pragma unroll
            for (int p = 0; p < 16; p++) s += red[p][cl][b];
            out[b * NC + c] = s;
        }
    }
}

// ---------------- launch ----------------
extern "C" void kernel_launch(void* const* d_in, const int* in_sizes, int n_in,
                              void* d_out, int out_size) {
    const int*   questions = (const int*)d_in[0];
    const int*   node_descs= (const int*)d_in[1];
    const int*   edge_src  = (const int*)d_in[2];
    const int*   edge_dst  = (const int*)d_in[3];
    const int*   edge_type = (const int*)d_in[4];
    const float* emb_word  = (const float*)d_in[5];
    const float* emb_desc  = (const float*)d_in[6];
    const float* Wx_f = (const float*)d_in[7];
    const float* Wh_f = (const float*)d_in[8];
    const float* bx_f = (const float*)d_in[9];
    const float* bh_f = (const float*)d_in[10];
    const float* Wx_b = (const float*)d_in[11];
    const float* Wh_b = (const float*)d_in[12];
    const float* bx_b = (const float*)d_in[13];
    const float* bh_b = (const float*)d_in[14];
    const float* W_hg = (const float*)d_in[15];
    const float* b_hg = (const float*)d_in[16];
    const float* bases = (const float*)d_in[17];
    const float* w_comp = (const float*)d_in[18];
    const float* rgcn_bias = (const float*)d_in[19];
    const float* W1 = (const float*)d_in[20];
    const float* b1 = (const float*)d_in[21];
    const float* W2 = (const float*)d_in[22];
    const float* b2 = (const float*)d_in[23];
    float* out = (float*)d_out;

    static cudaStream_t s1 = nullptr;
    static cudaEvent_t ev0 = nullptr, ev1 = nullptr, ev2 = nullptr, ev3 = nullptr;
    if (!s1) {
        cudaStreamCreateWithFlags(&s1, cudaStreamNonBlocking);
        cudaEventCreateWithFlags(&ev0, cudaEventDisableTiming);
        cudaEventCreateWithFlags(&ev1, cudaEventDisableTiming);
        cudaEventCreateWithFlags(&ev2, cudaEventDisableTiming);
        cudaEventCreateWithFlags(&ev3, cudaEventDisableTiming);
        cudaFuncSetAttribute(k_gru, cudaFuncAttributeMaxDynamicSharedMemorySize, SMEM_GRU);
    }

    cudaEventRecord(ev0, 0);
    cudaStreamWaitEvent(s1, ev0, 0);

    k_deg<<<(NE + 255) / 256, 256, 0, s1>>>(edge_dst);                     // 1 (s1)
    k_scan<<<1, 1024, 0, s1>>>();                                          // 2 (s1)
    k_gx<<<64, G3>>>(questions, emb_word, Wx_f, bx_f, Wx_b, bx_b);        // 3
    k_gru<<<8, G3, SMEM_GRU>>>(questions, Wh_f, bh_f, Wh_b, bh_b);        // 4 (ncu slot)
    cudaEventRecord(ev2, 0);
    k_perm<<<(NE + 255) / 256, 256, 0, s1>>>(edge_src, edge_dst, edge_type, w_comp); // 5 (s1)
    cudaEventRecord(ev1, s1);
    cudaStreamWaitEvent(s1, ev2, 0);
    k_hiddenQ<<<24, 128, 0, s1>>>(W1);                                     // 6 (s1, overlaps)
    cudaEventRecord(ev3, s1);
    k_svqg<<<(VD + 255) / 256, 256>>>(emb_desc, W_hg, b_hg);               // 7
    k_nf0<<<NN / NFW, 256>>>(node_descs, emb_desc);                        // 8
    cudaStreamWaitEvent(0, ev1, 0);
    k_agg<<<(NN * 2 * 32 + 255) / 256, 256>>>();                           // 9
    k_rgcn<<<RB, 256>>>(bases, rgcn_bias);                                 // 10
    k_hiddenP<<<8, 128>>>(W1);                                             // 11
    cudaStreamWaitEvent(0, ev3, 0);
    k_logits<<<63, 512>>>(W2, b1, b2, out);                                // 12
}

// round 16
// speedup vs baseline: 1.3019x; 1.0344x over previous
#include <cuda_runtime.h>
#include <cuda_fp16.h>
#include <math.h>

#define NN 20000
#define NE 320000
#define NR 200
#define DL 16
#define G  64
#define DW 300
#define DH 256
#define HD 128
#define NC 2000
#define VD 30000
#define BB 4
#define TT 32
#define G3 (3*HD)    // 384
#define BG (BB*G)    // 256
#define H1 1024
#define FEAT (G+DH)  // 320
#define RB 296       // rgcn blocks

// k_gru dyn smem (per (dir,batch) block): gx[TT*G3] + h[HD] + gh[G3] + msk[TT]
#define SMEM_GRU (TT*G3*4 + HD*4 + G3*4 + TT*4)   // 51328

// ---------------- scratch ----------------
__device__ float g_gx[2][BB][TT][G3];
__device__ float g_qemb[BB][DH];
__device__ float g_qg[BB][G];
__device__ float4 g_S[VD];           // per-vocab attention scores (b0..b3)
__device__ __half2 g_nf0h[NN][BG/2];
__device__ float g_sacc[NN][BG];
__device__ int   g_deg[NN];          // statically zero; re-zeroed by k_scan
__device__ int   g_off[NN+1];
__device__ int   g_cur[NN];
__device__ int   g_psrc[NE];
__device__ float g_pw[NE];
__device__ float g_pm[RB][BB];       // per-block softmax max
__device__ float g_pden[RB][BB];     // per-block softmax denom
__device__ float g_pagg[RB][BB][G];  // per-block weighted agg
__device__ float g_hidp[4][BB][H1];

// ---------------- helpers ----------------
__device__ __forceinline__ float sigm(float x) { return 1.f / (1.f + __expf(-x)); }
__device__ __forceinline__ float tanh_fast(float x) { return 2.f / (1.f + __expf(-2.f * x)) - 1.f; }

__device__ __forceinline__ void fma2(unsigned long long& d, unsigned long long a,
                                     unsigned long long b, unsigned long long c) {
    asm("fma.rn.f32x2 %0, %1, %2, %3;" : "=l"(d) : "l"(a), "l"(b), "l"(c));
}
__device__ __forceinline__ unsigned long long pk2(float x, float y) {
    unsigned long long r; asm("mov.b64 %0, {%1, %2};" : "=l"(r) : "f"(x), "f"(y)); return r;
}
__device__ __forceinline__ float2 upk2(unsigned long long v) {
    float2 f; asm("mov.b64 {%0, %1}, %2;" : "=f"(f.x), "=f"(f.y) : "l"(v)); return f;
}

// ---------------- kernels ----------------

// input gates gx = x @ Wx + bx.  64 blocks x 384 threads; double-buffered Wx loads.
__global__ __launch_bounds__(G3) void k_gx(const int* __restrict__ q,
                     const float* __restrict__ embw,
                     const float* __restrict__ WxF, const float* __restrict__ bxF,
                     const float* __restrict__ WxB, const float* __restrict__ bxB) {
    int d = blockIdx.x >> 5;
    int grp = blockIdx.x & 31;
    const float* Wx = d ? WxB : WxF;
    const float* bx = d ? bxB : bxF;
    __shared__ unsigned long long xs01[DW];
    __shared__ unsigned long long xs23[DW];
    int bt0 = grp * 4;
    int tok0 = q[((bt0 + 0) >> 5) * TT + ((bt0 + 0) & 31)];
    int tok1 = q[((bt0 + 1) >> 5) * TT + ((bt0 + 1) & 31)];
    int tok2 = q[((bt0 + 2) >> 5) * TT + ((bt0 + 2) & 31)];
    int tok3 = q[((bt0 + 3) >> 5) * TT + ((bt0 + 3) & 31)];
    for (int k = threadIdx.x; k < DW; k += blockDim.x) {
        float e0 = embw[tok0 * DW + k];
        float e1 = embw[tok1 * DW + k];
        float e2 = embw[tok2 * DW + k];
        float e3 = embw[tok3 * DW + k];
        xs01[k] = pk2(e0, e1);
        xs23[k] = pk2(e2, e3);
    }
    __syncthreads();
    int j = threadIdx.x;
    float bj = bx[j];
    unsigned long long a01 = pk2(bj, bj), a23 = a01;
    float wv[10];
    #pragma unroll
    for (int i = 0; i < 10; i++) wv[i] = Wx[i * G3 + j];
    #pragma unroll 1
    for (int k0 = 0; k0 < DW; k0 += 10) {
        float wn[10];
        int kn = (k0 + 10 < DW) ? (k0 + 10) : k0;
        #pragma unroll
        for (int i = 0; i < 10; i++) wn[i] = Wx[(kn + i) * G3 + j];
        #pragma unroll
        for (int i = 0; i < 10; i++) {
            unsigned long long wd = pk2(wv[i], wv[i]);
            fma2(a01, xs01[k0 + i], wd, a01);
            fma2(a23, xs23[k0 + i], wd, a23);
        }
        #pragma unroll
        for (int i = 0; i < 10; i++) wv[i] = wn[i];
    }
    float2 f01 = upk2(a01), f23 = upk2(a23);
    g_gx[d][(bt0 + 0) >> 5][(bt0 + 0) & 31][j] = f01.x;
    g_gx[d][(bt0 + 1) >> 5][(bt0 + 1) & 31][j] = f01.y;
    g_gx[d][(bt0 + 2) >> 5][(bt0 + 2) & 31][j] = f23.x;
    g_gx[d][(bt0 + 3) >> 5][(bt0 + 3) & 31][j] = f23.y;
}

// GRU recurrence. 8 blocks = (2 dirs x 4 batches) x 384 threads.
__global__ __launch_bounds__(G3, 1) void k_gru(const int* __restrict__ q,
                      const float* __restrict__ WhF, const float* __restrict__ bhF,
                      const float* __restrict__ WhB, const float* __restrict__ bhB) {
    extern __shared__ float sm[];
    float* gx_s = sm;                 // [TT*G3]
    float* h_s  = sm + TT * G3;       // [HD]
    float* gh   = h_s + HD;           // [G3]
    int*   msk  = (int*)(gh + G3);    // [TT]
    int d = blockIdx.x >> 2, b = blockIdx.x & 3;
    const float* Wh = d ? WhB : WhF;
    const float* bh = d ? bhB : bhF;
    int tid = threadIdx.x;
    {
        const float4* src = (const float4*)&g_gx[d][b][0][0];
        float4* dst = (float4*)gx_s;
        #pragma unroll
        for (int i = 0; i < 8; i++) dst[i * G3 + tid] = src[i * G3 + tid];
    }
    if (tid < TT) msk[tid] = (q[b * TT + tid] != 0);
    if (tid < HD) h_s[tid] = 0.f;
    float w[HD];
    #pragma unroll
    for (int k = 0; k < HD; k++) w[k] = Wh[k * G3 + tid];
    float bj = bh[tid];
    __syncthreads();
    for (int s = 0; s < TT; s++) {
        int t = d ? (TT - 1 - s) : s;
        float acc = bj;
        #pragma unroll
        for (int k = 0; k < HD; k++) acc = fmaf(h_s[k], w[k], acc);
        gh[tid] = acc;
        __syncthreads();
        if (tid < HD) {
            const float* gx = &gx_s[t * G3];
            int i = tid;
            float r = sigm(gx[i] + gh[i]);
            float z = sigm(gx[HD + i] + gh[HD + i]);
            float n = tanh_fast(gx[2 * HD + i] + r * gh[2 * HD + i]);
            float hn = (1.f - z) * n + z * h_s[i];
            if (msk[t]) h_s[i] = hn;
        }
        __syncthreads();
    }
    if (tid < HD) g_qemb[b][d * HD + tid] = h_s[tid];
}

// qg (block-redundant) + per-vocab scores S[v][b] = qg[b] . emb_desc[v].
__global__ void k_svqg(const float* __restrict__ embd,
                       const float* __restrict__ Whg, const float* __restrict__ bhg) {
    __shared__ float qs[BB][G];
    int tid = threadIdx.x;
    {
        int b = tid >> 6, g = tid & 63;
        float acc = bhg[g];
        #pragma unroll 8
        for (int k = 0; k < DH; k++) acc = fmaf(g_qemb[b][k], Whg[k * G + g], acc);
        qs[b][g] = acc;
        if (blockIdx.x == 0) g_qg[b][g] = acc;
    }
    __syncthreads();
    int v = blockIdx.x * 256 + tid;
    if (v >= VD) return;
    float s0 = 0.f, s1 = 0.f, s2 = 0.f, s3 = 0.f;
    const float4* row = (const float4*)&embd[v * G];
    #pragma unroll
    for (int g4 = 0; g4 < G / 4; g4++) {
        float4 e = row[g4];
        float4 q0 = *(float4*)&qs[0][g4 * 4];
        float4 q1 = *(float4*)&qs[1][g4 * 4];
        float4 q2 = *(float4*)&qs[2][g4 * 4];
        float4 q3 = *(float4*)&qs[3][g4 * 4];
        s0 += e.x * q0.x + e.y * q0.y + e.z * q0.z + e.w * q0.w;
        s1 += e.x * q1.x + e.y * q1.y + e.z * q1.z + e.w * q1.w;
        s2 += e.x * q2.x + e.y * q2.y + e.z * q2.z + e.w * q2.w;
        s3 += e.x * q3.x + e.y * q3.y + e.z * q3.z + e.w * q3.w;
    }
    g_S[v] = make_float4(s0, s1, s2, s3);
}

// desc attention -> nf0 (half2 out). Warp/node; scores via S-table lookup.
#define NFW 8
__global__ void k_nf0(const int* __restrict__ descs, const float* __restrict__ embd) {
    __shared__ float attnw[NFW][DL][BB];
    int tid = threadIdx.x, lane = tid & 31, wl = tid >> 5;
    int n = blockIdx.x * NFW + wl;
    int t16 = lane & 15, half = lane >> 4;
    int tok = descs[n * DL + t16];
    float4 sv = g_S[tok];
    float sa = half ? sv.y : sv.x;
    float sb = half ? sv.w : sv.z;
    float ma = sa, mb = sb;
    #pragma unroll
    for (int o = 1; o < 16; o <<= 1) {
        ma = fmaxf(ma, __shfl_xor_sync(0xFFFFFFFFu, ma, o));
        mb = fmaxf(mb, __shfl_xor_sync(0xFFFFFFFFu, mb, o));
    }
    float ea = __expf(sa - ma), eb = __expf(sb - mb);
    float da = ea, db = eb;
    #pragma unroll
    for (int o = 1; o < 16; o <<= 1) {
        da += __shfl_xor_sync(0xFFFFFFFFu, da, o);
        db += __shfl_xor_sync(0xFFFFFFFFu, db, o);
    }
    attnw[wl][t16][half]     = ea / da;
    attnw[wl][t16][2 + half] = eb / db;
    __syncwarp();
    float o00 = 0.f, o01 = 0.f, o10 = 0.f, o11 = 0.f;
    float o20 = 0.f, o21 = 0.f, o30 = 0.f, o31 = 0.f;
    #pragma unroll
    for (int t = 0; t < DL; t++) {
        int tk = __shfl_sync(0xFFFFFFFFu, tok, t);
        float2 x = *(const float2*)&embd[tk * G + 2 * lane];
        float4 w4 = *(float4*)&attnw[wl][t][0];
        o00 = fmaf(w4.x, x.x, o00); o01 = fmaf(w4.x, x.y, o01);
        o10 = fmaf(w4.y, x.x, o10); o11 = fmaf(w4.y, x.y, o11);
        o20 = fmaf(w4.z, x.x, o20); o21 = fmaf(w4.z, x.y, o21);
        o30 = fmaf(w4.w, x.x, o30); o31 = fmaf(w4.w, x.y, o31);
    }
    g_nf0h[n][0 * 32 + lane] = __floats2half2_rn(o00, o01);
    g_nf0h[n][1 * 32 + lane] = __floats2half2_rn(o10, o11);
    g_nf0h[n][2 * 32 + lane] = __floats2half2_rn(o20, o21);
    g_nf0h[n][3 * 32 + lane] = __floats2half2_rn(o30, o31);
}

__global__ void k_deg(const int* __restrict__ dst) {
    int e = blockIdx.x * blockDim.x + threadIdx.x;
    if (e < NE) atomicAdd(&g_deg[dst[e]], 1);
}

// single-block warp-shfl exclusive scan; re-zeroes g_deg for next replay
__global__ void k_scan() {
    __shared__ int wsum[32];
    __shared__ int carry;
    int tid = threadIdx.x, lane = tid & 31, wid = tid >> 5;
    if (tid == 0) carry = 0;
    __syncthreads();
    for (int base = 0; base < NN; base += 1024) {
        int idx = base + tid;
        int v = (idx < NN) ? g_deg[idx] : 0;
        if (idx < NN) g_deg[idx] = 0;
        int x = v;
        #pragma unroll
        for (int o = 1; o < 32; o <<= 1) {
            int y = __shfl_up_sync(0xFFFFFFFFu, x, o);
            if (lane >= o) x += y;
        }
        if (lane == 31) wsum[wid] = x;
        __syncthreads();
        if (wid == 0) {
            int s = wsum[lane];
            #pragma unroll
            for (int o = 1; o < 32; o <<= 1) {
                int y = __shfl_up_sync(0xFFFFFFFFu, s, o);
                if (lane >= o) s += y;
            }
            wsum[lane] = s;
        }
        __syncthreads();
        int ex = carry + (wid ? wsum[wid - 1] : 0) + x - v;
        if (idx < NN) { g_off[idx] = ex; g_cur[idx] = ex; }
        __syncthreads();
        if (tid == 0) carry += wsum[31];
        __syncthreads();
    }
    if (tid == 0) g_off[NN] = carry;
}

__global__ void k_perm(const int* __restrict__ src, const int* __restrict__ dst,
                       const int* __restrict__ et, const float* __restrict__ wcomp) {
    int e = blockIdx.x * blockDim.x + threadIdx.x;
    if (e >= NE) return;
    int pos = atomicAdd(&g_cur[dst[e]], 1);
    g_psrc[pos] = src[e];
    g_pw[pos]   = wcomp[et[e]];
}

// edge aggregation: 2 warps per dst node; 4-way batched edge loop for MLP.
__global__ void k_agg() {
    int gw = (blockIdx.x * blockDim.x + threadIdx.x) >> 5;
    int lane = threadIdx.x & 31;
    if (gw >= NN * 2) return;
    int n = gw >> 1, hb = gw & 1;
    int beg = g_off[n], end = g_off[n + 1];
    float a0 = 0.f, a1 = 0.f, a2 = 0.f, a3 = 0.f;
    int poff = hb * 64 + lane * 2;
    int i = beg;
    for (; i + 4 <= end; i += 4) {
        int s0 = g_psrc[i], s1 = g_psrc[i + 1], s2 = g_psrc[i + 2], s3 = g_psrc[i + 3];
        float w0 = g_pw[i], w1 = g_pw[i + 1], w2 = g_pw[i + 2], w3 = g_pw[i + 3];
        uint2 v0 = *(const uint2*)&g_nf0h[s0][poff];
        uint2 v1 = *(const uint2*)&g_nf0h[s1][poff];
        uint2 v2 = *(const uint2*)&g_nf0h[s2][poff];
        uint2 v3 = *(const uint2*)&g_nf0h[s3][poff];
        float2 f;
        f = __half22float2(*(__half2*)&v0.x); a0 = fmaf(w0, f.x, a0); a1 = fmaf(w0, f.y, a1);
        f = __half22float2(*(__half2*)&v0.y); a2 = fmaf(w0, f.x, a2); a3 = fmaf(w0, f.y, a3);
        f = __half22float2(*(__half2*)&v1.x); a0 = fmaf(w1, f.x, a0); a1 = fmaf(w1, f.y, a1);
        f = __half22float2(*(__half2*)&v1.y); a2 = fmaf(w1, f.x, a2); a3 = fmaf(w1, f.y, a3);
        f = __half22float2(*(__half2*)&v2.x); a0 = fmaf(w2, f.x, a0); a1 = fmaf(w2, f.y, a1);
        f = __half22float2(*(__half2*)&v2.y); a2 = fmaf(w2, f.x, a2); a3 = fmaf(w2, f.y, a3);
        f = __half22float2(*(__half2*)&v3.x); a0 = fmaf(w3, f.x, a0); a1 = fmaf(w3, f.y, a1);
        f = __half22float2(*(__half2*)&v3.y); a2 = fmaf(w3, f.x, a2); a3 = fmaf(w3, f.y, a3);
    }
    for (; i < end; i++) {
        int s = g_psrc[i];
        float w = g_pw[i];
        uint2 v = *(const uint2*)&g_nf0h[s][poff];
        float2 f0 = __half22float2(*(__half2*)&v.x), f1 = __half22float2(*(__half2*)&v.y);
        a0 = fmaf(w, f0.x, a0); a1 = fmaf(w, f0.y, a1);
        a2 = fmaf(w, f1.x, a2); a3 = fmaf(w, f1.y, a3);
    }
    *(float4*)&g_sacc[n][hb * 128 + lane * 4] = make_float4(a0, a1, a2, a3);
}

// nf1 = relu(s @ bases + bias) fused with ONLINE-SOFTMAX attention pooling.
// 2 barriers/iter: each thread sums its batch's two warp-partials directly.
__global__ void k_rgcn(const float* __restrict__ bases, const float* __restrict__ bias) {
    __shared__ float bs[G * G];
    __shared__ float srow[BG];
    __shared__ float swred[8];
    int tid = threadIdx.x;   // 256
    for (int i = tid; i < G * G; i += 256) bs[i] = bases[i];
    int b = tid >> 6, g = tid & 63;
    float bia = bias[g];
    float qv = g_qg[b][g];
    float m_run = -3.0e38f, den = 0.f, aggr = 0.f;
    float cur = g_sacc[blockIdx.x][tid];
    __syncthreads();
    for (int n = blockIdx.x; n < NN; n += RB) {
        srow[tid] = cur;
        __syncthreads();
        int nn = n + RB;
        float nxt = (nn < NN) ? g_sacc[nn][tid] : 0.f;
        float acc = bia;
        const float* sb = &srow[b * G];
        #pragma unroll 8
        for (int k = 0; k < G; k++) acc = fmaf(sb[k], bs[k * G + g], acc);
        acc = fmaxf(acc, 0.f);
        float p = acc * qv;
        p += __shfl_xor_sync(0xFFFFFFFFu, p, 16);
        p += __shfl_xor_sync(0xFFFFFFFFu, p, 8);
        p += __shfl_xor_sync(0xFFFFFFFFu, p, 4);
        p += __shfl_xor_sync(0xFFFFFFFFu, p, 2);
        p += __shfl_xor_sync(0xFFFFFFFFu, p, 1);
        if ((tid & 31) == 0) swred[tid >> 5] = p;
        __syncthreads();
        float sv = swred[2 * b] + swred[2 * b + 1];
        float m_new = fmaxf(m_run, sv);
        float sc = __expf(m_run - m_new);
        float e = __expf(sv - m_new);
        aggr = aggr * sc + e * acc;
        den  = den * sc + e;
        m_run = m_new;
        cur = nxt;
    }
    g_pagg[blockIdx.x][b][g] = aggr;
    if (g == 0) { g_pden[blockIdx.x][b] = den; g_pm[blockIdx.x][b] = m_run; }
}

// hidden partials, q_emb-only part (kp=1..3): 24 blocks x 128. Dep: gru only.
__global__ void k_hiddenQ(const float* __restrict__ W1) {
    int hb = blockIdx.x / 3, kp = 1 + blockIdx.x % 3;
    int tid = threadIdx.x;
    int h = hb * 128 + tid;
    int k0 = kp * 80;
    __shared__ float feat[BB][80];
    for (int i = tid; i < BB * 80; i += 128) {
        int b = i / 80, kk = i % 80;
        feat[b][kk] = g_qemb[b][k0 + kk - G];
    }
    __syncthreads();
    float a0 = 0.f, a1 = 0.f, a2 = 0.f, a3 = 0.f;
    #pragma unroll 4
    for (int kk = 0; kk < 80; kk++) {
        float w = W1[(k0 + kk) * H1 + h];
        a0 = fmaf(feat[0][kk], w, a0);
        a1 = fmaf(feat[1][kk], w, a1);
        a2 = fmaf(feat[2][kk], w, a2);
        a3 = fmaf(feat[3][kk], w, a3);
    }
    g_hidp[kp][0][h] = a0; g_hidp[kp][1][h] = a1;
    g_hidp[kp][2][h] = a2; g_hidp[kp][3][h] = a3;
}

// hidden partials, pool part (kp=0): 8 blocks x 128; fuses softmax combine.
__global__ void k_hiddenP(const float* __restrict__ W1) {
    int hb = blockIdx.x;
    int tid = threadIdx.x;
    int h = hb * 128 + tid;
    __shared__ float feat[BB][80];
    for (int i = tid; i < BB * 80; i += 128) {
        int b = i / 80, kk = i % 80;
        if (kk < G) {
            float m = -3.0e38f;
            #pragma unroll 4
            for (int r = 0; r < RB; r++) m = fmaxf(m, g_pm[r][b]);
            float acc = 0.f, den = 0.f;
            #pragma unroll 4
            for (int r = 0; r < RB; r++) {
                float sc = __expf(g_pm[r][b] - m);
                acc = fmaf(g_pagg[r][b][kk], sc, acc);
                den = fmaf(g_pden[r][b], sc, den);
            }
            feat[b][kk] = acc / den;
        } else {
            feat[b][kk] = g_qemb[b][kk - G];
        }
    }
    __syncthreads();
    float a0 = 0.f, a1 = 0.f, a2 = 0.f, a3 = 0.f;
    #pragma unroll 4
    for (int kk = 0; kk < 80; kk++) {
        float w = W1[kk * H1 + h];
        a0 = fmaf(feat[0][kk], w, a0);
        a1 = fmaf(feat[1][kk], w, a1);
        a2 = fmaf(feat[2][kk], w, a2);
        a3 = fmaf(feat[3][kk], w, a3);
    }
    g_hidp[0][0][h] = a0; g_hidp[0][1][h] = a1;
    g_hidp[0][2][h] = a2; g_hidp[0][3][h] = a3;
}

// logits: 63 blocks x 512 (16 k-parts x 32 classes); relu+bias fused.
__global__ void k_logits(const float* __restrict__ W2, const float* __restrict__ b1,
                         const float* __restrict__ b2, float* __restrict__ out) {
    __shared__ float hsm[BB][H1];
    __shared__ float red[16][32][BB];
    int tid = threadIdx.x;
    for (int i = tid; i < BB * H1; i += 512) {
        int b = i >> 10, k = i & (H1 - 1);
        float v = g_hidp[0][b][k] + g_hidp[1][b][k] + g_hidp[2][b][k] + g_hidp[3][b][k] + b1[k];
        hsm[b][k] = fmaxf(v, 0.f);
    }
    __syncthreads();
    int kp = tid >> 5, cl = tid & 31;
    int c = blockIdx.x * 32 + cl;
    float a0 = 0.f, a1 = 0.f, a2 = 0.f, a3 = 0.f;
    if (c < NC) {
        int k0 = kp * 64;
        #pragma unroll 4
        for (int k = k0; k < k0 + 64; k++) {
            float w = W2[k * NC + c];
            a0 = fmaf(hsm[0][k], w, a0);
            a1 = fmaf(hsm[1][k], w, a1);
            a2 = fmaf(hsm[2][k], w, a2);
            a3 = fmaf(hsm[3][k], w, a3);
        }
    }
    red[kp][cl][0] = a0; red[kp][cl][1] = a1; red[kp][cl][2] = a2; red[kp][cl][3] = a3;
    __syncthreads();
    if (kp == 0 && c < NC) {
        float bb2 = b2[c];
        #pragma unroll
        for (int b = 0; b < BB; b++) {
            float s = bb2;
            #pragma unroll
            for (int p = 0; p < 16; p++) s += red[p][cl][b];
            out[b * NC + c] = s;
        }
    }
}

// ---------------- launch ----------------
extern "C" void kernel_launch(void* const* d_in, const int* in_sizes, int n_in,
                              void* d_out, int out_size) {
    const int*   questions = (const int*)d_in[0];
    const int*   node_descs= (const int*)d_in[1];
    const int*   edge_src  = (const int*)d_in[2];
    const int*   edge_dst  = (const int*)d_in[3];
    const int*   edge_type = (const int*)d_in[4];
    const float* emb_word  = (const float*)d_in[5];
    const float* emb_desc  = (const float*)d_in[6];
    const float* Wx_f = (const float*)d_in[7];
    const float* Wh_f = (const float*)d_in[8];
    const float* bx_f = (const float*)d_in[9];
    const float* bh_f = (const float*)d_in[10];
    const float* Wx_b = (const float*)d_in[11];
    const float* Wh_b = (const float*)d_in[12];
    const float* bx_b = (const float*)d_in[13];
    const float* bh_b = (const float*)d_in[14];
    const float* W_hg = (const float*)d_in[15];
    const float* b_hg = (const float*)d_in[16];
    const float* bases = (const float*)d_in[17];
    const float* w_comp = (const float*)d_in[18];
    const float* rgcn_bias = (const float*)d_in[19];
    const float* W1 = (const float*)d_in[20];
    const float* b1 = (const float*)d_in[21];
    const float* W2 = (const float*)d_in[22];
    const float* b2 = (const float*)d_in[23];
    float* out = (float*)d_out;

    static cudaStream_t s1 = nullptr;
    static cudaEvent_t ev0 = nullptr, ev1 = nullptr, ev2 = nullptr, ev3 = nullptr;
    if (!s1) {
        cudaStreamCreateWithFlags(&s1, cudaStreamNonBlocking);
        cudaEventCreateWithFlags(&ev0, cudaEventDisableTiming);
        cudaEventCreateWithFlags(&ev1, cudaEventDisableTiming);
        cudaEventCreateWithFlags(&ev2, cudaEventDisableTiming);
        cudaEventCreateWithFlags(&ev3, cudaEventDisableTiming);
        cudaFuncSetAttribute(k_gru, cudaFuncAttributeMaxDynamicSharedMemorySize, SMEM_GRU);
    }

    // ev0 marks stream start; s1 work hangs off it so it EXECUTES from t=0
    // regardless of API call order below (graph deps, not call order).
    cudaEventRecord(ev0, 0);
    cudaStreamWaitEvent(s1, ev0, 0);

    k_gx<<<64, G3>>>(questions, emb_word, Wx_f, bx_f, Wx_b, bx_b);        // 1
    k_gru<<<8, G3, SMEM_GRU>>>(questions, Wh_f, bh_f, Wh_b, bh_b);        // 2
    cudaEventRecord(ev2, 0);
    k_svqg<<<(VD + 255) / 256, 256>>>(emb_desc, W_hg, b_hg);               // 3
    k_nf0<<<NN / NFW, 256>>>(node_descs, emb_desc);                        // 4 (ncu slot)
    k_deg<<<(NE + 255) / 256, 256, 0, s1>>>(edge_dst);                     // 5 (s1, runs from t=0)
    k_scan<<<1, 1024, 0, s1>>>();                                          // 6 (s1)
    k_perm<<<(NE + 255) / 256, 256, 0, s1>>>(edge_src, edge_dst, edge_type, w_comp); // 7 (s1)
    cudaEventRecord(ev1, s1);
    cudaStreamWaitEvent(s1, ev2, 0);
    k_hiddenQ<<<24, 128, 0, s1>>>(W1);                                     // 8 (s1)
    cudaEventRecord(ev3, s1);
    cudaStreamWaitEvent(0, ev1, 0);
    k_agg<<<(NN * 2 * 32 + 255) / 256, 256>>>();                           // 9
    k_rgcn<<<RB, 256>>>(bases, rgcn_bias);                                 // 10
    k_hiddenP<<<8, 128>>>(W1);                                             // 11
    cudaStreamWaitEvent(0, ev3, 0);
    k_logits<<<63, 512>>>(W2, b1, b2, out);                                // 12
}